// round 3
// baseline (speedup 1.0000x reference)
#include <cuda_runtime.h>
#include <math.h>

#define NN   32768
#define NX   64
#define KKK  16
#define EE   32
#define KE   512      // K*E
#define DYY  32
#define OUTC 4096     // NX*NX

// ---------------- scratch (device globals: no runtime allocation) -----------
__device__ float g_M[NN * KE];        // 64 MB: w*(1-h^2)
__device__ float g_P[NN * KE];        // 64 MB: w*h
__device__ float g_w[NN * KKK];       // 2 MB : softplus branch weights
__device__ float g_B[KE * OUTC];      // 8 MB : B[ke, o*64+i] = W2[k,e,o]*W1[k,i,e]
__device__ float g_W1t[NX * KE];      // 128KB: W1t[i, ke] = W1[k,i,e]

// ---------------- packed f32x2 FMA ------------------------------------------
__device__ __forceinline__ void ffma2(unsigned long long &c,
                                      unsigned long long a,
                                      unsigned long long b) {
    asm volatile("fma.rn.f32x2 %0, %1, %2, %0;" : "+l"(c) : "l"(a), "l"(b));
}
__device__ __forceinline__ float f2_lo(unsigned long long v) {
    return __uint_as_float((unsigned int)(v & 0xffffffffULL));
}
__device__ __forceinline__ float f2_hi(unsigned long long v) {
    return __uint_as_float((unsigned int)(v >> 32));
}

// ---------------- prep kernels ----------------------------------------------
__global__ void k_prep_w1t(const float* __restrict__ W1) {
    int idx = blockIdx.x * 256 + threadIdx.x;          // < 64*512
    int i  = idx >> 9;
    int ke = idx & 511;
    int k = ke >> 5, e = ke & 31;
    g_W1t[idx] = W1[(k << 11) + (i << 5) + e];
}

__global__ void k_prep_B(const float* __restrict__ W1,
                         const float* __restrict__ W2) {
    int idx = blockIdx.x * 256 + threadIdx.x;          // < 512*4096
    int ke = idx >> 12;
    int c  = idx & 4095;
    int o = c >> 6, i = c & 63;
    int k = ke >> 5, e = ke & 31;
    g_B[idx] = W2[(ke << 6) + o] * W1[(k << 11) + (i << 5) + e];
}

// ---------------- branch / bias / z0 (one warp per row) ---------------------
__global__ void __launch_bounds__(256)
k_branch(const float* __restrict__ x,   const float* __restrict__ y,
         const float* __restrict__ b2,
         const float* __restrict__ Wb1, const float* __restrict__ bb1,
         const float* __restrict__ Wb2, const float* __restrict__ bb2,
         const float* __restrict__ Wc1, const float* __restrict__ bc1,
         const float* __restrict__ Wc2, const float* __restrict__ bc2,
         const float* __restrict__ mean, const float* __restrict__ var,
         float* __restrict__ out_z) {
    __shared__ float sh[8 * 128];
    int warp = threadIdx.x >> 5;
    int lane = threadIdx.x & 31;
    int n = blockIdx.x * 8 + warp;

    float* yn = sh + warp * 128;   // 32
    float* t1 = yn + 32;           // 64
    float* t2 = yn + 96;           // 16
    float* wk = yn + 112;          // 16

    // y normalization + clip
    float v = (y[n * DYY + lane] - mean[lane]) * rsqrtf(var[lane]);
    yn[lane] = fminf(10.0f, fmaxf(-10.0f, v));
    __syncwarp();

    // t1 = relu(yn @ Wb1 + bb1)
    #pragma unroll
    for (int h = 0; h < 2; h++) {
        int j = lane + 32 * h;
        float s = bb1[j];
        #pragma unroll
        for (int d = 0; d < 32; d++) s += yn[d] * Wb1[d * 64 + j];
        t1[j] = fmaxf(s, 0.0f);
    }
    __syncwarp();

    if (lane < 16) {
        // weights = softplus(t1 @ Wb2 + bb2)
        float s = bb2[lane];
        #pragma unroll
        for (int j = 0; j < 64; j++) s += t1[j] * Wb2[j * 16 + lane];
        float w = fmaxf(s, 0.0f) + log1pf(expf(-fabsf(s)));
        wk[lane] = w;
        g_w[n * 16 + lane] = w;
        // t2 = relu(yn @ Wc1 + bc1)
        float s2 = bc1[lane];
        #pragma unroll
        for (int d = 0; d < 32; d++) s2 += yn[d] * Wc1[d * 16 + lane];
        t2[lane] = fmaxf(s2, 0.0f);
    }
    __syncwarp();

    // z0 = x + bias + w @ b2
    #pragma unroll
    for (int h = 0; h < 2; h++) {
        int o = lane + 32 * h;
        float s = x[n * 64 + o] + bc2[o];
        #pragma unroll
        for (int d = 0; d < 16; d++) s += t2[d] * Wc2[d * 64 + o];
        #pragma unroll
        for (int k = 0; k < 16; k++) s += wk[k] * b2[k * 64 + o];
        out_z[n * 64 + o] = s;
    }
}

// ---------------- h-GEMM: hpre = X @ W1t (+b1), tanh -> M, P ----------------
__global__ void __launch_bounds__(256)
k_hidden(const float* __restrict__ x, const float* __restrict__ b1) {
    __shared__ float Xs[16][128];      // [k][m]
    __shared__ float Ws[16][132];      // [k][ke_local]
    int ke0 = blockIdx.x * 128;
    int m0  = blockIdx.y * 128;
    int tid = threadIdx.x;
    int ty = tid >> 4, tx = tid & 15;

    float acc[8][8];
    #pragma unroll
    for (int i = 0; i < 8; i++)
        #pragma unroll
        for (int j = 0; j < 8; j++) acc[i][j] = 0.0f;

    for (int kt = 0; kt < 4; kt++) {
        __syncthreads();
        #pragma unroll
        for (int it = 0; it < 2; it++) {               // X tile 128x16
            int lin = tid + it * 256;
            int row = lin >> 2, c4 = lin & 3;
            float4 vv = *(const float4*)&x[(m0 + row) * 64 + kt * 16 + c4 * 4];
            Xs[c4 * 4 + 0][row] = vv.x;
            Xs[c4 * 4 + 1][row] = vv.y;
            Xs[c4 * 4 + 2][row] = vv.z;
            Xs[c4 * 4 + 3][row] = vv.w;
        }
        #pragma unroll
        for (int it = 0; it < 2; it++) {               // W1t tile 16x128
            int lin = tid + it * 256;
            int r = lin >> 5, c4 = lin & 31;
            float4 vv = *(const float4*)&g_W1t[(kt * 16 + r) * 512 + ke0 + c4 * 4];
            *(float4*)&Ws[r][c4 * 4] = vv;
        }
        __syncthreads();
        #pragma unroll
        for (int kk = 0; kk < 16; kk++) {
            float a[8], b[8];
            *(float4*)&a[0] = *(const float4*)&Xs[kk][ty * 8];
            *(float4*)&a[4] = *(const float4*)&Xs[kk][ty * 8 + 4];
            *(float4*)&b[0] = *(const float4*)&Ws[kk][tx * 8];
            *(float4*)&b[4] = *(const float4*)&Ws[kk][tx * 8 + 4];
            #pragma unroll
            for (int i = 0; i < 8; i++)
                #pragma unroll
                for (int j = 0; j < 8; j++) acc[i][j] += a[i] * b[j];
        }
    }

    // epilogue: tanh, weight, write M and P
    #pragma unroll
    for (int ii = 0; ii < 8; ii++) {
        int n = m0 + ty * 8 + ii;
        float mvals[8], pvals[8];
        #pragma unroll
        for (int jj = 0; jj < 8; jj++) {
            int keg = ke0 + tx * 8 + jj;
            float h = tanhf(acc[ii][jj] + b1[keg]);
            float w = g_w[n * 16 + (keg >> 5)];
            mvals[jj] = w * (1.0f - h * h);
            pvals[jj] = w * h;
        }
        int base = n * 512 + ke0 + tx * 8;
        *(float4*)&g_M[base]     = make_float4(mvals[0], mvals[1], mvals[2], mvals[3]);
        *(float4*)&g_M[base + 4] = make_float4(mvals[4], mvals[5], mvals[6], mvals[7]);
        *(float4*)&g_P[base]     = make_float4(pvals[0], pvals[1], pvals[2], pvals[3]);
        *(float4*)&g_P[base + 4] = make_float4(pvals[4], pvals[5], pvals[6], pvals[7]);
    }
}

// ---------------- z-GEMM: out_z += P @ W2 (512x64) --------------------------
__global__ void __launch_bounds__(256)
k_zgemm(const float* __restrict__ W2, float* __restrict__ out_z) {
    __shared__ float Ps[32][128];
    __shared__ float Vs[32][68];
    int m0 = blockIdx.x * 128;
    int tid = threadIdx.x;
    int ty = tid >> 4, tx = tid & 15;

    float acc[8][4];
    #pragma unroll
    for (int i = 0; i < 8; i++)
        #pragma unroll
        for (int j = 0; j < 4; j++) acc[i][j] = 0.0f;

    for (int kt = 0; kt < 16; kt++) {
        __syncthreads();
        #pragma unroll
        for (int it = 0; it < 4; it++) {               // P tile 128x32
            int lin = tid + it * 256;
            int row = lin >> 3, c4 = lin & 7;
            float4 vv = *(const float4*)&g_P[(m0 + row) * 512 + kt * 32 + c4 * 4];
            Ps[c4 * 4 + 0][row] = vv.x;
            Ps[c4 * 4 + 1][row] = vv.y;
            Ps[c4 * 4 + 2][row] = vv.z;
            Ps[c4 * 4 + 3][row] = vv.w;
        }
        #pragma unroll
        for (int it = 0; it < 2; it++) {               // W2 tile 32x64
            int lin = tid + it * 256;
            int r = lin >> 4, c4 = lin & 15;
            *(float4*)&Vs[r][c4 * 4] = *(const float4*)&W2[(kt * 32 + r) * 64 + c4 * 4];
        }
        __syncthreads();
        #pragma unroll
        for (int kk = 0; kk < 32; kk++) {
            float a[8], b[4];
            *(float4*)&a[0] = *(const float4*)&Ps[kk][ty * 8];
            *(float4*)&a[4] = *(const float4*)&Ps[kk][ty * 8 + 4];
            *(float4*)&b[0] = *(const float4*)&Vs[kk][tx * 4];
            #pragma unroll
            for (int i = 0; i < 8; i++)
                #pragma unroll
                for (int j = 0; j < 4; j++) acc[i][j] += a[i] * b[j];
        }
    }

    #pragma unroll
    for (int ii = 0; ii < 8; ii++) {
        int n = m0 + ty * 8 + ii;
        float4* p = (float4*)&out_z[n * 64 + tx * 4];
        float4 cur = *p;
        cur.x += acc[ii][0]; cur.y += acc[ii][1];
        cur.z += acc[ii][2]; cur.w += acc[ii][3];
        *p = cur;
    }
}

// ---------------- main Jacobian GEMM: out_j = I + M @ B ---------------------
// 128x128 tile, BK=16, 256 threads, 8x8/thread via packed fma.rn.f32x2.
// Pairs along M (natural from shared A), B duplicated in shared so an LDS.64
// yields a ready (b,b) pack on conflict-free banks (col map tx + 16*jj).
__global__ void __launch_bounds__(256)
k_jac(float* __restrict__ out_j) {
    __shared__ float As[16][128];       // [k][m]
    __shared__ float Bsd[16][256];      // [k][2*c] duplicated pairs
    int c0 = blockIdx.x * 128;
    int m0 = blockIdx.y * 128;
    int tid = threadIdx.x;
    int ty = tid >> 4, tx = tid & 15;

    unsigned long long cc[4][8];
    #pragma unroll
    for (int i = 0; i < 4; i++)
        #pragma unroll
        for (int j = 0; j < 8; j++) cc[i][j] = 0ULL;   // (0.f, 0.f)

    for (int kt = 0; kt < 32; kt++) {
        // prefetch global tiles into regs
        float4 av[2], bv[2];
        #pragma unroll
        for (int it = 0; it < 2; it++) {
            int lin = tid + it * 256;                  // A: 128x16
            int row = lin >> 2, c4 = lin & 3;
            av[it] = *(const float4*)&g_M[(m0 + row) * 512 + kt * 16 + c4 * 4];
            int r = lin >> 5, cc4 = lin & 31;          // B: 16x128
            bv[it] = *(const float4*)&g_B[(size_t)(kt * 16 + r) * 4096 + c0 + cc4 * 4];
        }
        __syncthreads();
        #pragma unroll
        for (int it = 0; it < 2; it++) {
            int lin = tid + it * 256;
            int row = lin >> 2, c4 = lin & 3;
            As[c4 * 4 + 0][row] = av[it].x;
            As[c4 * 4 + 1][row] = av[it].y;
            As[c4 * 4 + 2][row] = av[it].z;
            As[c4 * 4 + 3][row] = av[it].w;
            int r = lin >> 5, cc4 = lin & 31;
            *(float2*)&Bsd[r][(cc4 * 4 + 0) * 2] = make_float2(bv[it].x, bv[it].x);
            *(float2*)&Bsd[r][(cc4 * 4 + 1) * 2] = make_float2(bv[it].y, bv[it].y);
            *(float2*)&Bsd[r][(cc4 * 4 + 2) * 2] = make_float2(bv[it].z, bv[it].z);
            *(float2*)&Bsd[r][(cc4 * 4 + 3) * 2] = make_float2(bv[it].w, bv[it].w);
        }
        __syncthreads();

        #pragma unroll
        for (int kk = 0; kk < 16; kk++) {
            unsigned long long a2[4], b[8];
            {
                ulonglong2 u0 = *(const ulonglong2*)&As[kk][ty * 8];
                ulonglong2 u1 = *(const ulonglong2*)&As[kk][ty * 8 + 4];
                a2[0] = u0.x; a2[1] = u0.y; a2[2] = u1.x; a2[3] = u1.y;
            }
            #pragma unroll
            for (int jj = 0; jj < 8; jj++)
                b[jj] = *(const unsigned long long*)&Bsd[kk][2 * (tx + 16 * jj)];
            #pragma unroll
            for (int i2 = 0; i2 < 4; i2++)
                #pragma unroll
                for (int jj = 0; jj < 8; jj++)
                    ffma2(cc[i2][jj], a2[i2], b[jj]);
        }
    }

    // epilogue: add identity (col c = o*64+i is diagonal iff c % 65 == 0)
    #pragma unroll
    for (int i2 = 0; i2 < 4; i2++) {
        size_t n0 = (size_t)(m0 + ty * 8 + i2 * 2);
        #pragma unroll
        for (int jj = 0; jj < 8; jj++) {
            int c = c0 + tx + 16 * jj;
            float add = ((c % 65) == 0) ? 1.0f : 0.0f;
            out_j[n0 * 4096 + c]       = f2_lo(cc[i2][jj]) + add;
            out_j[(n0 + 1) * 4096 + c] = f2_hi(cc[i2][jj]) + add;
        }
    }
}

// ---------------- launch ----------------------------------------------------
extern "C" void kernel_launch(void* const* d_in, const int* in_sizes, int n_in,
                              void* d_out, int out_size) {
    const float* x    = (const float*)d_in[0];
    const float* y    = (const float*)d_in[1];
    const float* W1   = (const float*)d_in[2];
    const float* b1   = (const float*)d_in[3];
    const float* W2   = (const float*)d_in[4];
    const float* b2   = (const float*)d_in[5];
    const float* Wb1  = (const float*)d_in[6];
    const float* bb1  = (const float*)d_in[7];
    const float* Wb2  = (const float*)d_in[8];
    const float* bb2  = (const float*)d_in[9];
    const float* Wc1  = (const float*)d_in[10];
    const float* bc1  = (const float*)d_in[11];
    const float* Wc2  = (const float*)d_in[12];
    const float* bc2  = (const float*)d_in[13];
    const float* mean = (const float*)d_in[14];
    const float* var  = (const float*)d_in[15];

    float* out   = (float*)d_out;
    float* out_z = out;                       // N*64
    float* out_j = out + (size_t)NN * NX;     // N*4096

    k_prep_w1t<<<128, 256>>>(W1);
    k_prep_B<<<8192, 256>>>(W1, W2);
    k_branch<<<NN / 8, 256>>>(x, y, b2, Wb1, bb1, Wb2, bb2,
                              Wc1, bc1, Wc2, bc2, mean, var, out_z);
    k_hidden<<<dim3(4, NN / 128), 256>>>(x, b1);
    k_zgemm<<<NN / 128, 256>>>(W2, out_z);
    k_jac<<<dim3(32, NN / 128), 256>>>(out_j);
}

// round 6
// speedup vs baseline: 3.0612x; 3.0612x over previous
#include <cuda_runtime.h>
#include <cuda_bf16.h>
#include <math.h>
#include <stdint.h>

#define NN   32768
#define NX   64
#define KKK  16
#define EE   32
#define KE   512      // K*E
#define DYY  32
#define OUTC 4096     // NX*NX

// ---------------- scratch (device globals: no runtime allocation) -----------
__device__ __nv_bfloat16 g_Mh[NN * KE];   // 32 MB: hi(w*(1-h^2))
__device__ __nv_bfloat16 g_Ml[NN * KE];   // 32 MB: lo residual
__device__ float         g_P [NN * KE];   // 64 MB: w*h (fp32, z path)
__device__ float         g_w [NN * KKK];  //  2 MB: softplus branch weights
__device__ __nv_bfloat16 g_Bh[OUTC * KE]; //  4 MB: hi(B^T[c][ke])
__device__ __nv_bfloat16 g_Bl[OUTC * KE]; //  4 MB: lo residual
__device__ float         g_W1t[NX * KE];  // 128KB: W1t[i, ke] = W1[k,i,e]

// ================= PTX helpers (base sm_103 features only) ===================
__device__ __forceinline__ uint32_t smem_u32(const void* p) {
    uint32_t a;
    asm("{ .reg .u64 t; cvta.to.shared.u64 t, %1; cvt.u32.u64 %0, t; }"
        : "=r"(a) : "l"(p));
    return a;
}

#define CPA16(dst, src) \
    asm volatile("cp.async.cg.shared.global [%0], [%1], 16;" \
                 :: "r"((uint32_t)(dst)), "l"(src))

__device__ __forceinline__ void ldsm4(uint32_t* r, uint32_t addr) {
    asm volatile("ldmatrix.sync.aligned.m8n8.x4.shared.b16 {%0,%1,%2,%3}, [%4];"
                 : "=r"(r[0]), "=r"(r[1]), "=r"(r[2]), "=r"(r[3]) : "r"(addr));
}

__device__ __forceinline__ void mma16816(float* c, const uint32_t* a,
                                         uint32_t b0, uint32_t b1) {
    asm volatile(
        "mma.sync.aligned.m16n8k16.row.col.f32.bf16.bf16.f32 "
        "{%0,%1,%2,%3}, {%4,%5,%6,%7}, {%8,%9}, {%0,%1,%2,%3};"
        : "+f"(c[0]), "+f"(c[1]), "+f"(c[2]), "+f"(c[3])
        : "r"(a[0]), "r"(a[1]), "r"(a[2]), "r"(a[3]), "r"(b0), "r"(b1));
}

// ---------------- prep kernels ----------------------------------------------
__global__ void k_prep_w1t(const float* __restrict__ W1) {
    int idx = blockIdx.x * 256 + threadIdx.x;          // < 64*512
    int i  = idx >> 9;
    int ke = idx & 511;
    int k = ke >> 5, e = ke & 31;
    g_W1t[idx] = W1[(k << 11) + (i << 5) + e];
}

// B^T[c][ke] = W2[k,e,o] * W1[k,i,e], c = o*64+i  (bf16 hi/lo split)
__global__ void k_prep_Bt(const float* __restrict__ W1,
                          const float* __restrict__ W2) {
    int idx = blockIdx.x * 256 + threadIdx.x;          // < 4096*512
    int c  = idx >> 9;
    int ke = idx & 511;
    int o = c >> 6, i = c & 63;
    int k = ke >> 5, e = ke & 31;
    float v = W2[(ke << 6) + o] * W1[(k << 11) + (i << 5) + e];
    __nv_bfloat16 hi = __float2bfloat16(v);
    __nv_bfloat16 lo = __float2bfloat16(v - __bfloat162float(hi));
    g_Bh[idx] = hi;
    g_Bl[idx] = lo;
}

// ---------------- branch / bias / z0 (one warp per row) ---------------------
__global__ void __launch_bounds__(256)
k_branch(const float* __restrict__ x,   const float* __restrict__ y,
         const float* __restrict__ b2,
         const float* __restrict__ Wb1, const float* __restrict__ bb1,
         const float* __restrict__ Wb2, const float* __restrict__ bb2,
         const float* __restrict__ Wc1, const float* __restrict__ bc1,
         const float* __restrict__ Wc2, const float* __restrict__ bc2,
         const float* __restrict__ mean, const float* __restrict__ var,
         float* __restrict__ out_z) {
    __shared__ float sh[8 * 128];
    int warp = threadIdx.x >> 5;
    int lane = threadIdx.x & 31;
    int n = blockIdx.x * 8 + warp;

    float* yn = sh + warp * 128;   // 32
    float* t1 = yn + 32;           // 64
    float* t2 = yn + 96;           // 16
    float* wk = yn + 112;          // 16

    float v = (y[n * DYY + lane] - mean[lane]) * rsqrtf(var[lane]);
    yn[lane] = fminf(10.0f, fmaxf(-10.0f, v));
    __syncwarp();

    #pragma unroll
    for (int h = 0; h < 2; h++) {
        int j = lane + 32 * h;
        float s = bb1[j];
        #pragma unroll
        for (int d = 0; d < 32; d++) s += yn[d] * Wb1[d * 64 + j];
        t1[j] = fmaxf(s, 0.0f);
    }
    __syncwarp();

    if (lane < 16) {
        float s = bb2[lane];
        #pragma unroll
        for (int j = 0; j < 64; j++) s += t1[j] * Wb2[j * 16 + lane];
        float w = fmaxf(s, 0.0f) + log1pf(expf(-fabsf(s)));
        wk[lane] = w;
        g_w[n * 16 + lane] = w;
        float s2 = bc1[lane];
        #pragma unroll
        for (int d = 0; d < 32; d++) s2 += yn[d] * Wc1[d * 16 + lane];
        t2[lane] = fmaxf(s2, 0.0f);
    }
    __syncwarp();

    #pragma unroll
    for (int h = 0; h < 2; h++) {
        int o = lane + 32 * h;
        float s = x[n * 64 + o] + bc2[o];
        #pragma unroll
        for (int d = 0; d < 16; d++) s += t2[d] * Wc2[d * 64 + o];
        #pragma unroll
        for (int k = 0; k < 16; k++) s += wk[k] * b2[k * 64 + o];
        out_z[n * 64 + o] = s;
    }
}

// ---------------- h-GEMM: hpre = X @ W1t (+b1), tanh -> Mh/Ml, P ------------
__global__ void __launch_bounds__(256)
k_hidden(const float* __restrict__ x, const float* __restrict__ b1) {
    __shared__ float Xs[16][128];      // [k][m]
    __shared__ float Ws[16][132];      // [k][ke_local]
    int ke0 = blockIdx.x * 128;
    int m0  = blockIdx.y * 128;
    int tid = threadIdx.x;
    int ty = tid >> 4, tx = tid & 15;

    float acc[8][8];
    #pragma unroll
    for (int i = 0; i < 8; i++)
        #pragma unroll
        for (int j = 0; j < 8; j++) acc[i][j] = 0.0f;

    for (int kt = 0; kt < 4; kt++) {
        __syncthreads();
        #pragma unroll
        for (int it = 0; it < 2; it++) {               // X tile 128x16
            int lin = tid + it * 256;
            int row = lin >> 2, c4 = lin & 3;
            float4 vv = *(const float4*)&x[(m0 + row) * 64 + kt * 16 + c4 * 4];
            Xs[c4 * 4 + 0][row] = vv.x;
            Xs[c4 * 4 + 1][row] = vv.y;
            Xs[c4 * 4 + 2][row] = vv.z;
            Xs[c4 * 4 + 3][row] = vv.w;
        }
        #pragma unroll
        for (int it = 0; it < 2; it++) {               // W1t tile 16x128
            int lin = tid + it * 256;
            int r = lin >> 5, c4 = lin & 31;
            float4 vv = *(const float4*)&g_W1t[(kt * 16 + r) * 512 + ke0 + c4 * 4];
            *(float4*)&Ws[r][c4 * 4] = vv;
        }
        __syncthreads();
        #pragma unroll
        for (int kk = 0; kk < 16; kk++) {
            float a[8], b[8];
            *(float4*)&a[0] = *(const float4*)&Xs[kk][ty * 8];
            *(float4*)&a[4] = *(const float4*)&Xs[kk][ty * 8 + 4];
            *(float4*)&b[0] = *(const float4*)&Ws[kk][tx * 8];
            *(float4*)&b[4] = *(const float4*)&Ws[kk][tx * 8 + 4];
            #pragma unroll
            for (int i = 0; i < 8; i++)
                #pragma unroll
                for (int j = 0; j < 8; j++) acc[i][j] += a[i] * b[j];
        }
    }

    // epilogue: tanh, weight, bf16 split of M, fp32 P
    #pragma unroll
    for (int ii = 0; ii < 8; ii++) {
        int n = m0 + ty * 8 + ii;
        float pvals[8];
        uint32_t hh[4], ll[4];
        #pragma unroll
        for (int q = 0; q < 4; q++) {
            uint32_t hp = 0, lp = 0;
            #pragma unroll
            for (int s = 0; s < 2; s++) {
                int jj = q * 2 + s;
                int keg = ke0 + tx * 8 + jj;
                float h = tanhf(acc[ii][jj] + b1[keg]);
                float w = g_w[n * 16 + (keg >> 5)];
                float m = w * (1.0f - h * h);
                pvals[jj] = w * h;
                __nv_bfloat16 mh = __float2bfloat16(m);
                __nv_bfloat16 ml = __float2bfloat16(m - __bfloat162float(mh));
                hp |= ((uint32_t)__bfloat16_as_ushort(mh)) << (16 * s);
                lp |= ((uint32_t)__bfloat16_as_ushort(ml)) << (16 * s);
            }
            hh[q] = hp; ll[q] = lp;
        }
        int base = n * 512 + ke0 + tx * 8;
        *(uint4*)&g_Mh[base] = make_uint4(hh[0], hh[1], hh[2], hh[3]);
        *(uint4*)&g_Ml[base] = make_uint4(ll[0], ll[1], ll[2], ll[3]);
        *(float4*)&g_P[base]     = make_float4(pvals[0], pvals[1], pvals[2], pvals[3]);
        *(float4*)&g_P[base + 4] = make_float4(pvals[4], pvals[5], pvals[6], pvals[7]);
    }
}

// ---------------- z-GEMM: out_z += P @ W2 (512x64) --------------------------
__global__ void __launch_bounds__(256)
k_zgemm(const float* __restrict__ W2, float* __restrict__ out_z) {
    __shared__ float Ps[32][128];
    __shared__ float Vs[32][68];
    int m0 = blockIdx.x * 128;
    int tid = threadIdx.x;
    int ty = tid >> 4, tx = tid & 15;

    float acc[8][4];
    #pragma unroll
    for (int i = 0; i < 8; i++)
        #pragma unroll
        for (int j = 0; j < 4; j++) acc[i][j] = 0.0f;

    for (int kt = 0; kt < 16; kt++) {
        __syncthreads();
        #pragma unroll
        for (int it = 0; it < 4; it++) {               // P tile 128x32
            int lin = tid + it * 256;
            int row = lin >> 3, c4 = lin & 7;
            float4 vv = *(const float4*)&g_P[(m0 + row) * 512 + kt * 32 + c4 * 4];
            Ps[c4 * 4 + 0][row] = vv.x;
            Ps[c4 * 4 + 1][row] = vv.y;
            Ps[c4 * 4 + 2][row] = vv.z;
            Ps[c4 * 4 + 3][row] = vv.w;
        }
        #pragma unroll
        for (int it = 0; it < 2; it++) {               // W2 tile 32x64
            int lin = tid + it * 256;
            int r = lin >> 4, c4 = lin & 15;
            *(float4*)&Vs[r][c4 * 4] = *(const float4*)&W2[(kt * 32 + r) * 64 + c4 * 4];
        }
        __syncthreads();
        #pragma unroll
        for (int kk = 0; kk < 32; kk++) {
            float a[8], b[4];
            *(float4*)&a[0] = *(const float4*)&Ps[kk][ty * 8];
            *(float4*)&a[4] = *(const float4*)&Ps[kk][ty * 8 + 4];
            *(float4*)&b[0] = *(const float4*)&Vs[kk][tx * 4];
            #pragma unroll
            for (int i = 0; i < 8; i++)
                #pragma unroll
                for (int j = 0; j < 4; j++) acc[i][j] += a[i] * b[j];
        }
    }

    #pragma unroll
    for (int ii = 0; ii < 8; ii++) {
        int n = m0 + ty * 8 + ii;
        float4* p = (float4*)&out_z[n * 64 + tx * 4];
        float4 cur = *p;
        cur.x += acc[ii][0]; cur.y += acc[ii][1];
        cur.z += acc[ii][2]; cur.w += acc[ii][3];
        *p = cur;
    }
}

// ---------------- jac GEMM via mma.sync bf16 3-pass split -------------------
// out_j(32768x4096) = I + M(32768x512) @ B(512x4096)
// CTA tile 128(M) x 256(N), 8 warps (2m x 4n), warp tile 64x64.
// K chunks of 64, double-buffered cp.async, SW128-swizzled smem for ldmatrix.
// Stage layout: Ah 16K | Al 16K | Bh 32K | Bl 32K = 96KB; 2 stages = 192KB.
#define J_TM 128
#define J_TN 256
#define J_KB 64
#define J_NKT 8
#define J_ST_SZ 98304
#define J_SMEM (2 * J_ST_SZ)

__device__ __forceinline__ void j_issue(uint32_t stage, int m0, int c0,
                                        int kt, int tid) {
    const char* pMh = (const char*)g_Mh;
    const char* pMl = (const char*)g_Ml;
    const char* pBh = (const char*)g_Bh;
    const char* pBl = (const char*)g_Bl;
    #pragma unroll
    for (int i = 0; i < 4; i++) {                  // A: 128 rows x 8 x 16B
        int lin = tid + i * 256;
        int r = lin >> 3, c = lin & 7;
        uint32_t off = r * 128 + c * 16;
        uint32_t sw = off ^ ((off >> 3) & 0x70);
        size_t go = ((size_t)(m0 + r) * 512 + kt * J_KB + c * 8) * 2;
        CPA16(stage + sw,         pMh + go);
        CPA16(stage + 16384 + sw, pMl + go);
    }
    #pragma unroll
    for (int i = 0; i < 8; i++) {                  // B: 256 rows x 8 x 16B
        int lin = tid + i * 256;
        int r = lin >> 3, c = lin & 7;
        uint32_t off = r * 128 + c * 16;
        uint32_t sw = off ^ ((off >> 3) & 0x70);
        size_t go = ((size_t)(c0 + r) * 512 + kt * J_KB + c * 8) * 2;
        CPA16(stage + 32768 + sw, pBh + go);
        CPA16(stage + 65536 + sw, pBl + go);
    }
    asm volatile("cp.async.commit_group;" ::: "memory");
}

__global__ void __launch_bounds__(256, 1)
k_jac_mma(float* __restrict__ out_j) {
    extern __shared__ char smem[];
    const uint32_t sb = smem_u32(smem);
    const int tid  = threadIdx.x;
    const int lane = tid & 31;
    const int wid  = tid >> 5;
    const int wm   = wid >> 2;      // 0..1
    const int wn   = wid & 3;       // 0..3
    const int c0 = blockIdx.x * J_TN;
    const int m0 = blockIdx.y * J_TM;

    // ldmatrix per-thread address components
    const int a_row = wm * 64 + (lane & 15);
    const int a_t   = (a_row & 7) << 4;
    const int a_kl  = (lane >> 4) * 16;            // bytes
    const uint32_t a_base = (uint32_t)a_row * 128;
    const int b_row = wn * 64 + ((lane & 16) >> 1) + (lane & 7);
    const int b_t   = (b_row & 7) << 4;
    const int b_kl  = (lane & 8) * 2;              // bytes
    const uint32_t b_base = (uint32_t)b_row * 128;

    float acc[4][8][4];
    #pragma unroll
    for (int mt = 0; mt < 4; mt++)
        #pragma unroll
        for (int nt = 0; nt < 8; nt++)
            #pragma unroll
            for (int q = 0; q < 4; q++) acc[mt][nt][q] = 0.0f;

    j_issue(sb,           m0, c0, 0, tid);
    j_issue(sb + J_ST_SZ, m0, c0, 1, tid);

    for (int kt = 0; kt < J_NKT; kt++) {
        if (kt < J_NKT - 1)
            asm volatile("cp.async.wait_group 1;" ::: "memory");
        else
            asm volatile("cp.async.wait_group 0;" ::: "memory");
        __syncthreads();

        const uint32_t st = sb + (kt & 1) * J_ST_SZ;
        const uint32_t sAh = st, sAl = st + 16384;
        const uint32_t sBh = st + 32768, sBl = st + 65536;

        #pragma unroll
        for (int kk = 0; kk < 4; kk++) {
            const uint32_t akc = (uint32_t)((kk * 32 + a_kl) ^ a_t);
            const uint32_t bkc = (uint32_t)((kk * 32 + b_kl) ^ b_t);
            uint32_t Ah[4][4], Al[4][4], Bx[4][4];
            #pragma unroll
            for (int mt = 0; mt < 4; mt++) {
                ldsm4(Ah[mt], sAh + a_base + mt * 2048 + akc);
                ldsm4(Al[mt], sAl + a_base + mt * 2048 + akc);
            }
            #pragma unroll
            for (int nt = 0; nt < 4; nt++)
                ldsm4(Bx[nt], sBh + b_base + nt * 2048 + bkc);
            // pass hh + lh (Bh resident)
            #pragma unroll
            for (int mt = 0; mt < 4; mt++)
                #pragma unroll
                for (int nt = 0; nt < 4; nt++) {
                    mma16816(acc[mt][nt * 2],     Ah[mt], Bx[nt][0], Bx[nt][1]);
                    mma16816(acc[mt][nt * 2 + 1], Ah[mt], Bx[nt][2], Bx[nt][3]);
                    mma16816(acc[mt][nt * 2],     Al[mt], Bx[nt][0], Bx[nt][1]);
                    mma16816(acc[mt][nt * 2 + 1], Al[mt], Bx[nt][2], Bx[nt][3]);
                }
            // pass hl (reload B as Bl)
            #pragma unroll
            for (int nt = 0; nt < 4; nt++)
                ldsm4(Bx[nt], sBl + b_base + nt * 2048 + bkc);
            #pragma unroll
            for (int mt = 0; mt < 4; mt++)
                #pragma unroll
                for (int nt = 0; nt < 4; nt++) {
                    mma16816(acc[mt][nt * 2],     Ah[mt], Bx[nt][0], Bx[nt][1]);
                    mma16816(acc[mt][nt * 2 + 1], Ah[mt], Bx[nt][2], Bx[nt][3]);
                }
        }
        __syncthreads();
        if (kt + 2 < J_NKT)
            j_issue(sb + (kt & 1) * J_ST_SZ, m0, c0, kt + 2, tid);
    }

    // epilogue: identity on columns with c % 65 == 0 (independent of row)
    #pragma unroll
    for (int mt = 0; mt < 4; mt++) {
        size_t r0 = (size_t)m0 + wm * 64 + mt * 16 + (lane >> 2);
        #pragma unroll
        for (int nt = 0; nt < 8; nt++) {
            int c = c0 + wn * 64 + nt * 8 + 2 * (lane & 3);
            float add0 = ((c % 65) == 0) ? 1.0f : 0.0f;
            float add1 = (((c + 1) % 65) == 0) ? 1.0f : 0.0f;
            float2 v0 = make_float2(acc[mt][nt][0] + add0, acc[mt][nt][1] + add1);
            float2 v1 = make_float2(acc[mt][nt][2] + add0, acc[mt][nt][3] + add1);
            *(float2*)&out_j[r0 * 4096 + c]       = v0;
            *(float2*)&out_j[(r0 + 8) * 4096 + c] = v1;
        }
    }
}

// ---------------- launch ----------------------------------------------------
extern "C" void kernel_launch(void* const* d_in, const int* in_sizes, int n_in,
                              void* d_out, int out_size) {
    const float* x    = (const float*)d_in[0];
    const float* y    = (const float*)d_in[1];
    const float* W1   = (const float*)d_in[2];
    const float* b1   = (const float*)d_in[3];
    const float* W2   = (const float*)d_in[4];
    const float* b2   = (const float*)d_in[5];
    const float* Wb1  = (const float*)d_in[6];
    const float* bb1  = (const float*)d_in[7];
    const float* Wb2  = (const float*)d_in[8];
    const float* bb2  = (const float*)d_in[9];
    const float* Wc1  = (const float*)d_in[10];
    const float* bc1  = (const float*)d_in[11];
    const float* Wc2  = (const float*)d_in[12];
    const float* bc2  = (const float*)d_in[13];
    const float* mean = (const float*)d_in[14];
    const float* var  = (const float*)d_in[15];

    float* out   = (float*)d_out;
    float* out_z = out;                       // N*64
    float* out_j = out + (size_t)NN * NX;     // N*4096

    cudaFuncSetAttribute(k_jac_mma, cudaFuncAttributeMaxDynamicSharedMemorySize,
                         J_SMEM);

    k_prep_w1t<<<128, 256>>>(W1);
    k_prep_Bt<<<8192, 256>>>(W1, W2);
    k_branch<<<NN / 8, 256>>>(x, y, b2, Wb1, bb1, Wb2, bb2,
                              Wc1, bc1, Wc2, bc2, mean, var, out_z);
    k_hidden<<<dim3(4, NN / 128), 256>>>(x, b1);
    k_zgemm<<<NN / 128, 256>>>(W2, out_z);
    k_jac_mma<<<dim3(OUTC / J_TN, NN / J_TM), 256, J_SMEM>>>(out_j);
}

// round 7
// speedup vs baseline: 3.9697x; 1.2968x over previous
#include <cuda_runtime.h>
#include <cuda_fp16.h>
#include <math.h>
#include <stdint.h>

#define NN   32768
#define NX   64
#define KKK  16
#define EE   32
#define KE   512      // K*E
#define DYY  32
#define OUTC 4096     // NX*NX

// ---------------- scratch (device globals: no runtime allocation) -----------
__device__ __half g_Mh[NN * KE];   // 32 MB: hi(w*(1-h^2))  fp16
__device__ __half g_Ml[NN * KE];   // 32 MB: lo residual    fp16
__device__ float  g_P [NN * KE];   // 64 MB: w*h (fp32, z path)
__device__ float  g_w [NN * KKK];  //  2 MB: softplus branch weights
__device__ __half g_Bh[OUTC * KE]; //  4 MB: fp16(B^T[c][ke])
__device__ float  g_W1t[NX * KE];  // 128KB: W1t[i, ke] = W1[k,i,e]

// ================= PTX helpers (base sm_103 features only) ===================
__device__ __forceinline__ uint32_t smem_u32(const void* p) {
    uint32_t a;
    asm("{ .reg .u64 t; cvta.to.shared.u64 t, %1; cvt.u32.u64 %0, t; }"
        : "=r"(a) : "l"(p));
    return a;
}

#define CPA16(dst, src) \
    asm volatile("cp.async.cg.shared.global [%0], [%1], 16;" \
                 :: "r"((uint32_t)(dst)), "l"(src))

__device__ __forceinline__ void ldsm4(uint32_t* r, uint32_t addr) {
    asm volatile("ldmatrix.sync.aligned.m8n8.x4.shared.b16 {%0,%1,%2,%3}, [%4];"
                 : "=r"(r[0]), "=r"(r[1]), "=r"(r[2]), "=r"(r[3]) : "r"(addr));
}

__device__ __forceinline__ void mma16816(float* c, const uint32_t* a,
                                         uint32_t b0, uint32_t b1) {
    asm volatile(
        "mma.sync.aligned.m16n8k16.row.col.f32.f16.f16.f32 "
        "{%0,%1,%2,%3}, {%4,%5,%6,%7}, {%8,%9}, {%0,%1,%2,%3};"
        : "+f"(c[0]), "+f"(c[1]), "+f"(c[2]), "+f"(c[3])
        : "r"(a[0]), "r"(a[1]), "r"(a[2]), "r"(a[3]), "r"(b0), "r"(b1));
}

// ---------------- prep kernels ----------------------------------------------
__global__ void k_prep_w1t(const float* __restrict__ W1) {
    int idx = blockIdx.x * 256 + threadIdx.x;          // < 64*512
    int i  = idx >> 9;
    int ke = idx & 511;
    int k = ke >> 5, e = ke & 31;
    g_W1t[idx] = W1[(k << 11) + (i << 5) + e];
}

// B^T[c][ke] = W2[k,e,o] * W1[k,i,e], c = o*64+i  (single fp16)
__global__ void k_prep_Bt(const float* __restrict__ W1,
                          const float* __restrict__ W2) {
    int idx = blockIdx.x * 256 + threadIdx.x;          // < 4096*512
    int c  = idx >> 9;
    int ke = idx & 511;
    int o = c >> 6, i = c & 63;
    int k = ke >> 5, e = ke & 31;
    float v = W2[(ke << 6) + o] * W1[(k << 11) + (i << 5) + e];
    g_Bh[idx] = __float2half_rn(v);
}

// ---------------- branch / bias / z0 (one warp per row) ---------------------
__global__ void __launch_bounds__(256)
k_branch(const float* __restrict__ x,   const float* __restrict__ y,
         const float* __restrict__ b2,
         const float* __restrict__ Wb1, const float* __restrict__ bb1,
         const float* __restrict__ Wb2, const float* __restrict__ bb2,
         const float* __restrict__ Wc1, const float* __restrict__ bc1,
         const float* __restrict__ Wc2, const float* __restrict__ bc2,
         const float* __restrict__ mean, const float* __restrict__ var,
         float* __restrict__ out_z) {
    __shared__ float sh[8 * 128];
    int warp = threadIdx.x >> 5;
    int lane = threadIdx.x & 31;
    int n = blockIdx.x * 8 + warp;

    float* yn = sh + warp * 128;   // 32
    float* t1 = yn + 32;           // 64
    float* t2 = yn + 96;           // 16
    float* wk = yn + 112;          // 16

    float v = (y[n * DYY + lane] - mean[lane]) * rsqrtf(var[lane]);
    yn[lane] = fminf(10.0f, fmaxf(-10.0f, v));
    __syncwarp();

    #pragma unroll
    for (int h = 0; h < 2; h++) {
        int j = lane + 32 * h;
        float s = bb1[j];
        #pragma unroll
        for (int d = 0; d < 32; d++) s += yn[d] * Wb1[d * 64 + j];
        t1[j] = fmaxf(s, 0.0f);
    }
    __syncwarp();

    if (lane < 16) {
        float s = bb2[lane];
        #pragma unroll
        for (int j = 0; j < 64; j++) s += t1[j] * Wb2[j * 16 + lane];
        float w = fmaxf(s, 0.0f) + log1pf(expf(-fabsf(s)));
        wk[lane] = w;
        g_w[n * 16 + lane] = w;
        float s2 = bc1[lane];
        #pragma unroll
        for (int d = 0; d < 32; d++) s2 += yn[d] * Wc1[d * 16 + lane];
        t2[lane] = fmaxf(s2, 0.0f);
    }
    __syncwarp();

    #pragma unroll
    for (int h = 0; h < 2; h++) {
        int o = lane + 32 * h;
        float s = x[n * 64 + o] + bc2[o];
        #pragma unroll
        for (int d = 0; d < 16; d++) s += t2[d] * Wc2[d * 64 + o];
        #pragma unroll
        for (int k = 0; k < 16; k++) s += wk[k] * b2[k * 64 + o];
        out_z[n * 64 + o] = s;
    }
}

// ---------------- h-GEMM: hpre = X @ W1t (+b1), tanh -> Mh/Ml, P ------------
__global__ void __launch_bounds__(256)
k_hidden(const float* __restrict__ x, const float* __restrict__ b1) {
    __shared__ float Xs[16][128];      // [k][m]
    __shared__ float Ws[16][132];      // [k][ke_local]
    int ke0 = blockIdx.x * 128;
    int m0  = blockIdx.y * 128;
    int tid = threadIdx.x;
    int ty = tid >> 4, tx = tid & 15;

    float acc[8][8];
    #pragma unroll
    for (int i = 0; i < 8; i++)
        #pragma unroll
        for (int j = 0; j < 8; j++) acc[i][j] = 0.0f;

    for (int kt = 0; kt < 4; kt++) {
        __syncthreads();
        #pragma unroll
        for (int it = 0; it < 2; it++) {               // X tile 128x16
            int lin = tid + it * 256;
            int row = lin >> 2, c4 = lin & 3;
            float4 vv = *(const float4*)&x[(m0 + row) * 64 + kt * 16 + c4 * 4];
            Xs[c4 * 4 + 0][row] = vv.x;
            Xs[c4 * 4 + 1][row] = vv.y;
            Xs[c4 * 4 + 2][row] = vv.z;
            Xs[c4 * 4 + 3][row] = vv.w;
        }
        #pragma unroll
        for (int it = 0; it < 2; it++) {               // W1t tile 16x128
            int lin = tid + it * 256;
            int r = lin >> 5, c4 = lin & 31;
            float4 vv = *(const float4*)&g_W1t[(kt * 16 + r) * 512 + ke0 + c4 * 4];
            *(float4*)&Ws[r][c4 * 4] = vv;
        }
        __syncthreads();
        #pragma unroll
        for (int kk = 0; kk < 16; kk++) {
            float a[8], b[8];
            *(float4*)&a[0] = *(const float4*)&Xs[kk][ty * 8];
            *(float4*)&a[4] = *(const float4*)&Xs[kk][ty * 8 + 4];
            *(float4*)&b[0] = *(const float4*)&Ws[kk][tx * 8];
            *(float4*)&b[4] = *(const float4*)&Ws[kk][tx * 8 + 4];
            #pragma unroll
            for (int i = 0; i < 8; i++)
                #pragma unroll
                for (int j = 0; j < 8; j++) acc[i][j] += a[i] * b[j];
        }
    }

    // epilogue: tanh, weight, fp16 split of M, fp32 P
    #pragma unroll
    for (int ii = 0; ii < 8; ii++) {
        int n = m0 + ty * 8 + ii;
        float pvals[8];
        uint32_t hh[4], ll[4];
        #pragma unroll
        for (int q = 0; q < 4; q++) {
            uint32_t hp = 0, lp = 0;
            #pragma unroll
            for (int s = 0; s < 2; s++) {
                int jj = q * 2 + s;
                int keg = ke0 + tx * 8 + jj;
                float h = tanhf(acc[ii][jj] + b1[keg]);
                float w = g_w[n * 16 + (keg >> 5)];
                float m = w * (1.0f - h * h);
                pvals[jj] = w * h;
                __half mh = __float2half_rn(m);
                __half ml = __float2half_rn(m - __half2float(mh));
                hp |= ((uint32_t)__half_as_ushort(mh)) << (16 * s);
                lp |= ((uint32_t)__half_as_ushort(ml)) << (16 * s);
            }
            hh[q] = hp; ll[q] = lp;
        }
        int base = n * 512 + ke0 + tx * 8;
        *(uint4*)&g_Mh[base] = make_uint4(hh[0], hh[1], hh[2], hh[3]);
        *(uint4*)&g_Ml[base] = make_uint4(ll[0], ll[1], ll[2], ll[3]);
        *(float4*)&g_P[base]     = make_float4(pvals[0], pvals[1], pvals[2], pvals[3]);
        *(float4*)&g_P[base + 4] = make_float4(pvals[4], pvals[5], pvals[6], pvals[7]);
    }
}

// ---------------- z-GEMM: out_z += P @ W2 (512x64) --------------------------
__global__ void __launch_bounds__(256)
k_zgemm(const float* __restrict__ W2, float* __restrict__ out_z) {
    __shared__ float Ps[32][128];
    __shared__ float Vs[32][68];
    int m0 = blockIdx.x * 128;
    int tid = threadIdx.x;
    int ty = tid >> 4, tx = tid & 15;

    float acc[8][4];
    #pragma unroll
    for (int i = 0; i < 8; i++)
        #pragma unroll
        for (int j = 0; j < 4; j++) acc[i][j] = 0.0f;

    for (int kt = 0; kt < 16; kt++) {
        __syncthreads();
        #pragma unroll
        for (int it = 0; it < 4; it++) {               // P tile 128x32
            int lin = tid + it * 256;
            int row = lin >> 3, c4 = lin & 7;
            float4 vv = *(const float4*)&g_P[(m0 + row) * 512 + kt * 32 + c4 * 4];
            Ps[c4 * 4 + 0][row] = vv.x;
            Ps[c4 * 4 + 1][row] = vv.y;
            Ps[c4 * 4 + 2][row] = vv.z;
            Ps[c4 * 4 + 3][row] = vv.w;
        }
        #pragma unroll
        for (int it = 0; it < 2; it++) {               // W2 tile 32x64
            int lin = tid + it * 256;
            int r = lin >> 4, c4 = lin & 15;
            *(float4*)&Vs[r][c4 * 4] = *(const float4*)&W2[(kt * 32 + r) * 64 + c4 * 4];
        }
        __syncthreads();
        #pragma unroll
        for (int kk = 0; kk < 32; kk++) {
            float a[8], b[4];
            *(float4*)&a[0] = *(const float4*)&Ps[kk][ty * 8];
            *(float4*)&a[4] = *(const float4*)&Ps[kk][ty * 8 + 4];
            *(float4*)&b[0] = *(const float4*)&Vs[kk][tx * 4];
            #pragma unroll
            for (int i = 0; i < 8; i++)
                #pragma unroll
                for (int j = 0; j < 4; j++) acc[i][j] += a[i] * b[j];
        }
    }

    #pragma unroll
    for (int ii = 0; ii < 8; ii++) {
        int n = m0 + ty * 8 + ii;
        float4* p = (float4*)&out_z[n * 64 + tx * 4];
        float4 cur = *p;
        cur.x += acc[ii][0]; cur.y += acc[ii][1];
        cur.z += acc[ii][2]; cur.w += acc[ii][3];
        *p = cur;
    }
}

// ---------------- jac GEMM via mma.sync fp16 2-pass split -------------------
// out_j(32768x4096) = I + M(32768x512) @ B(512x4096)
//   = I + (Mh + Ml) @ fp16(B)   (dropped term ~2^-12 relative)
// CTA tile 128(M) x 256(N), 8 warps (2m x 4n), warp tile 64x64.
// K chunks of 64, double-buffered cp.async, SW128-swizzled smem for ldmatrix.
// Stage layout: Ah 16K | Al 16K | Bh 32K = 64KB; 2 stages = 128KB.
#define J_TM 128
#define J_TN 256
#define J_KB 64
#define J_NKT 8
#define J_ST_SZ 65536
#define J_SMEM (2 * J_ST_SZ)

__device__ __forceinline__ void j_issue(uint32_t stage, int m0, int c0,
                                        int kt, int tid) {
    const char* pMh = (const char*)g_Mh;
    const char* pMl = (const char*)g_Ml;
    const char* pBh = (const char*)g_Bh;
    #pragma unroll
    for (int i = 0; i < 4; i++) {                  // A: 128 rows x 8 x 16B
        int lin = tid + i * 256;
        int r = lin >> 3, c = lin & 7;
        uint32_t off = r * 128 + c * 16;
        uint32_t sw = off ^ ((off >> 3) & 0x70);
        size_t go = ((size_t)(m0 + r) * 512 + kt * J_KB + c * 8) * 2;
        CPA16(stage + sw,         pMh + go);
        CPA16(stage + 16384 + sw, pMl + go);
    }
    #pragma unroll
    for (int i = 0; i < 8; i++) {                  // B: 256 rows x 8 x 16B
        int lin = tid + i * 256;
        int r = lin >> 3, c = lin & 7;
        uint32_t off = r * 128 + c * 16;
        uint32_t sw = off ^ ((off >> 3) & 0x70);
        size_t go = ((size_t)(c0 + r) * 512 + kt * J_KB + c * 8) * 2;
        CPA16(stage + 32768 + sw, pBh + go);
    }
    asm volatile("cp.async.commit_group;" ::: "memory");
}

__global__ void __launch_bounds__(256, 1)
k_jac_mma(float* __restrict__ out_j) {
    extern __shared__ char smem[];
    const uint32_t sb = smem_u32(smem);
    const int tid  = threadIdx.x;
    const int lane = tid & 31;
    const int wid  = tid >> 5;
    const int wm   = wid >> 2;      // 0..1
    const int wn   = wid & 3;       // 0..3
    const int c0 = blockIdx.x * J_TN;
    const int m0 = blockIdx.y * J_TM;

    // ldmatrix per-thread address components
    const int a_row = wm * 64 + (lane & 15);
    const int a_t   = (a_row & 7) << 4;
    const int a_kl  = (lane >> 4) * 16;            // bytes
    const uint32_t a_base = (uint32_t)a_row * 128;
    const int b_row = wn * 64 + ((lane & 16) >> 1) + (lane & 7);
    const int b_t   = (b_row & 7) << 4;
    const int b_kl  = (lane & 8) * 2;              // bytes
    const uint32_t b_base = (uint32_t)b_row * 128;

    float acc[4][8][4];
    #pragma unroll
    for (int mt = 0; mt < 4; mt++)
        #pragma unroll
        for (int nt = 0; nt < 8; nt++)
            #pragma unroll
            for (int q = 0; q < 4; q++) acc[mt][nt][q] = 0.0f;

    j_issue(sb,           m0, c0, 0, tid);
    j_issue(sb + J_ST_SZ, m0, c0, 1, tid);

    for (int kt = 0; kt < J_NKT; kt++) {
        if (kt < J_NKT - 1)
            asm volatile("cp.async.wait_group 1;" ::: "memory");
        else
            asm volatile("cp.async.wait_group 0;" ::: "memory");
        __syncthreads();

        const uint32_t st = sb + (kt & 1) * J_ST_SZ;
        const uint32_t sAh = st, sAl = st + 16384;
        const uint32_t sBh = st + 32768;

        #pragma unroll
        for (int kk = 0; kk < 4; kk++) {
            const uint32_t akc = (uint32_t)((kk * 32 + a_kl) ^ a_t);
            const uint32_t bkc = (uint32_t)((kk * 32 + b_kl) ^ b_t);
            uint32_t Ah[4][4], Al[4][4], Bx[4][4];
            #pragma unroll
            for (int mt = 0; mt < 4; mt++) {
                ldsm4(Ah[mt], sAh + a_base + mt * 2048 + akc);
                ldsm4(Al[mt], sAl + a_base + mt * 2048 + akc);
            }
            #pragma unroll
            for (int nt = 0; nt < 4; nt++)
                ldsm4(Bx[nt], sBh + b_base + nt * 2048 + bkc);
            // passes hh + lh (exact A times fp16 B)
            #pragma unroll
            for (int mt = 0; mt < 4; mt++)
                #pragma unroll
                for (int nt = 0; nt < 4; nt++) {
                    mma16816(acc[mt][nt * 2],     Ah[mt], Bx[nt][0], Bx[nt][1]);
                    mma16816(acc[mt][nt * 2 + 1], Ah[mt], Bx[nt][2], Bx[nt][3]);
                    mma16816(acc[mt][nt * 2],     Al[mt], Bx[nt][0], Bx[nt][1]);
                    mma16816(acc[mt][nt * 2 + 1], Al[mt], Bx[nt][2], Bx[nt][3]);
                }
        }
        __syncthreads();
        if (kt + 2 < J_NKT)
            j_issue(sb + (kt & 1) * J_ST_SZ, m0, c0, kt + 2, tid);
    }

    // epilogue: identity on columns with c % 65 == 0 (independent of row)
    #pragma unroll
    for (int mt = 0; mt < 4; mt++) {
        size_t r0 = (size_t)m0 + wm * 64 + mt * 16 + (lane >> 2);
        #pragma unroll
        for (int nt = 0; nt < 8; nt++) {
            int c = c0 + wn * 64 + nt * 8 + 2 * (lane & 3);
            float add0 = ((c % 65) == 0) ? 1.0f : 0.0f;
            float add1 = (((c + 1) % 65) == 0) ? 1.0f : 0.0f;
            float2 v0 = make_float2(acc[mt][nt][0] + add0, acc[mt][nt][1] + add1);
            float2 v1 = make_float2(acc[mt][nt][2] + add0, acc[mt][nt][3] + add1);
            *(float2*)&out_j[r0 * 4096 + c]       = v0;
            *(float2*)&out_j[(r0 + 8) * 4096 + c] = v1;
        }
    }
}

// ---------------- launch ----------------------------------------------------
extern "C" void kernel_launch(void* const* d_in, const int* in_sizes, int n_in,
                              void* d_out, int out_size) {
    const float* x    = (const float*)d_in[0];
    const float* y    = (const float*)d_in[1];
    const float* W1   = (const float*)d_in[2];
    const float* b1   = (const float*)d_in[3];
    const float* W2   = (const float*)d_in[4];
    const float* b2   = (const float*)d_in[5];
    const float* Wb1  = (const float*)d_in[6];
    const float* bb1  = (const float*)d_in[7];
    const float* Wb2  = (const float*)d_in[8];
    const float* bb2  = (const float*)d_in[9];
    const float* Wc1  = (const float*)d_in[10];
    const float* bc1  = (const float*)d_in[11];
    const float* Wc2  = (const float*)d_in[12];
    const float* bc2  = (const float*)d_in[13];
    const float* mean = (const float*)d_in[14];
    const float* var  = (const float*)d_in[15];

    float* out   = (float*)d_out;
    float* out_z = out;                       // N*64
    float* out_j = out + (size_t)NN * NX;     // N*4096

    cudaFuncSetAttribute(k_jac_mma, cudaFuncAttributeMaxDynamicSharedMemorySize,
                         J_SMEM);

    k_prep_w1t<<<128, 256>>>(W1);
    k_prep_Bt<<<8192, 256>>>(W1, W2);
    k_branch<<<NN / 8, 256>>>(x, y, b2, Wb1, bb1, Wb2, bb2,
                              Wc1, bc1, Wc2, bc2, mean, var, out_z);
    k_hidden<<<dim3(4, NN / 128), 256>>>(x, b1);
    k_zgemm<<<NN / 128, 256>>>(W2, out_z);
    k_jac_mma<<<dim3(OUTC / J_TN, NN / J_TM), 256, J_SMEM>>>(out_j);
}

// round 8
// speedup vs baseline: 5.5394x; 1.3954x over previous
#include <cuda_runtime.h>
#include <cuda_fp16.h>
#include <math.h>
#include <stdint.h>

#define NN   32768
#define NX   64
#define KKK  16
#define EE   32
#define KE   512      // K*E
#define DYY  32
#define OUTC 4096     // NX*NX

// ---------------- scratch (device globals: no runtime allocation) -----------
__device__ __half g_Mh[NN * KE];   // 32 MB: fp16(w*(1-h^2))
__device__ float  g_P [NN * KE];   // 64 MB: w*h (fp32, z path)
__device__ float  g_w [NN * KKK];  //  2 MB: softplus branch weights
__device__ __half g_Bh[OUTC * KE]; //  4 MB: fp16(B^T[c][ke])
__device__ float  g_W1t[NX * KE];  // 128KB: W1t[i, ke] = W1[k,i,e]

// ================= PTX helpers (base sm_103 features only) ===================
__device__ __forceinline__ uint32_t smem_u32(const void* p) {
    uint32_t a;
    asm("{ .reg .u64 t; cvta.to.shared.u64 t, %1; cvt.u32.u64 %0, t; }"
        : "=r"(a) : "l"(p));
    return a;
}

#define CPA16(dst, src) \
    asm volatile("cp.async.cg.shared.global [%0], [%1], 16;" \
                 :: "r"((uint32_t)(dst)), "l"(src))

__device__ __forceinline__ void ldsm4(uint32_t* r, uint32_t addr) {
    asm volatile("ldmatrix.sync.aligned.m8n8.x4.shared.b16 {%0,%1,%2,%3}, [%4];"
                 : "=r"(r[0]), "=r"(r[1]), "=r"(r[2]), "=r"(r[3]) : "r"(addr));
}

__device__ __forceinline__ void mma16816(float* c, const uint32_t* a,
                                         uint32_t b0, uint32_t b1) {
    asm volatile(
        "mma.sync.aligned.m16n8k16.row.col.f32.f16.f16.f32 "
        "{%0,%1,%2,%3}, {%4,%5,%6,%7}, {%8,%9}, {%0,%1,%2,%3};"
        : "+f"(c[0]), "+f"(c[1]), "+f"(c[2]), "+f"(c[3])
        : "r"(a[0]), "r"(a[1]), "r"(a[2]), "r"(a[3]), "r"(b0), "r"(b1));
}

// ---------------- prep kernels ----------------------------------------------
__global__ void k_prep_w1t(const float* __restrict__ W1) {
    int idx = blockIdx.x * 256 + threadIdx.x;          // < 64*512
    int i  = idx >> 9;
    int ke = idx & 511;
    int k = ke >> 5, e = ke & 31;
    g_W1t[idx] = W1[(k << 11) + (i << 5) + e];
}

// B^T[c][ke] = W2[k,e,o] * W1[k,i,e], c = o*64+i  (single fp16)
__global__ void k_prep_Bt(const float* __restrict__ W1,
                          const float* __restrict__ W2) {
    int idx = blockIdx.x * 256 + threadIdx.x;          // < 4096*512
    int c  = idx >> 9;
    int ke = idx & 511;
    int o = c >> 6, i = c & 63;
    int k = ke >> 5, e = ke & 31;
    float v = W2[(ke << 6) + o] * W1[(k << 11) + (i << 5) + e];
    g_Bh[idx] = __float2half_rn(v);
}

// ---------------- branch / bias / z0 (one warp per row) ---------------------
__global__ void __launch_bounds__(256)
k_branch(const float* __restrict__ x,   const float* __restrict__ y,
         const float* __restrict__ b2,
         const float* __restrict__ Wb1, const float* __restrict__ bb1,
         const float* __restrict__ Wb2, const float* __restrict__ bb2,
         const float* __restrict__ Wc1, const float* __restrict__ bc1,
         const float* __restrict__ Wc2, const float* __restrict__ bc2,
         const float* __restrict__ mean, const float* __restrict__ var,
         float* __restrict__ out_z) {
    __shared__ float sh[8 * 128];
    int warp = threadIdx.x >> 5;
    int lane = threadIdx.x & 31;
    int n = blockIdx.x * 8 + warp;

    float* yn = sh + warp * 128;   // 32
    float* t1 = yn + 32;           // 64
    float* t2 = yn + 96;           // 16
    float* wk = yn + 112;          // 16

    float v = (y[n * DYY + lane] - mean[lane]) * rsqrtf(var[lane]);
    yn[lane] = fminf(10.0f, fmaxf(-10.0f, v));
    __syncwarp();

    #pragma unroll
    for (int h = 0; h < 2; h++) {
        int j = lane + 32 * h;
        float s = bb1[j];
        #pragma unroll
        for (int d = 0; d < 32; d++) s += yn[d] * Wb1[d * 64 + j];
        t1[j] = fmaxf(s, 0.0f);
    }
    __syncwarp();

    if (lane < 16) {
        float s = bb2[lane];
        #pragma unroll
        for (int j = 0; j < 64; j++) s += t1[j] * Wb2[j * 16 + lane];
        float w = fmaxf(s, 0.0f) + log1pf(expf(-fabsf(s)));
        wk[lane] = w;
        g_w[n * 16 + lane] = w;
        float s2 = bc1[lane];
        #pragma unroll
        for (int d = 0; d < 32; d++) s2 += yn[d] * Wc1[d * 16 + lane];
        t2[lane] = fmaxf(s2, 0.0f);
    }
    __syncwarp();

    #pragma unroll
    for (int h = 0; h < 2; h++) {
        int o = lane + 32 * h;
        float s = x[n * 64 + o] + bc2[o];
        #pragma unroll
        for (int d = 0; d < 16; d++) s += t2[d] * Wc2[d * 64 + o];
        #pragma unroll
        for (int k = 0; k < 16; k++) s += wk[k] * b2[k * 64 + o];
        out_z[n * 64 + o] = s;
    }
}

// ---------------- h-GEMM: hpre = X @ W1t (+b1), tanh -> Mh, P ---------------
__global__ void __launch_bounds__(256)
k_hidden(const float* __restrict__ x, const float* __restrict__ b1) {
    __shared__ float Xs[16][128];      // [k][m]
    __shared__ float Ws[16][132];      // [k][ke_local]
    int ke0 = blockIdx.x * 128;
    int m0  = blockIdx.y * 128;
    int tid = threadIdx.x;
    int ty = tid >> 4, tx = tid & 15;

    float acc[8][8];
    #pragma unroll
    for (int i = 0; i < 8; i++)
        #pragma unroll
        for (int j = 0; j < 8; j++) acc[i][j] = 0.0f;

    for (int kt = 0; kt < 4; kt++) {
        __syncthreads();
        #pragma unroll
        for (int it = 0; it < 2; it++) {               // X tile 128x16
            int lin = tid + it * 256;
            int row = lin >> 2, c4 = lin & 3;
            float4 vv = *(const float4*)&x[(m0 + row) * 64 + kt * 16 + c4 * 4];
            Xs[c4 * 4 + 0][row] = vv.x;
            Xs[c4 * 4 + 1][row] = vv.y;
            Xs[c4 * 4 + 2][row] = vv.z;
            Xs[c4 * 4 + 3][row] = vv.w;
        }
        #pragma unroll
        for (int it = 0; it < 2; it++) {               // W1t tile 16x128
            int lin = tid + it * 256;
            int r = lin >> 5, c4 = lin & 31;
            float4 vv = *(const float4*)&g_W1t[(kt * 16 + r) * 512 + ke0 + c4 * 4];
            *(float4*)&Ws[r][c4 * 4] = vv;
        }
        __syncthreads();
        #pragma unroll
        for (int kk = 0; kk < 16; kk++) {
            float a[8], b[8];
            *(float4*)&a[0] = *(const float4*)&Xs[kk][ty * 8];
            *(float4*)&a[4] = *(const float4*)&Xs[kk][ty * 8 + 4];
            *(float4*)&b[0] = *(const float4*)&Ws[kk][tx * 8];
            *(float4*)&b[4] = *(const float4*)&Ws[kk][tx * 8 + 4];
            #pragma unroll
            for (int i = 0; i < 8; i++)
                #pragma unroll
                for (int j = 0; j < 8; j++) acc[i][j] += a[i] * b[j];
        }
    }

    // epilogue: tanh, weight, fp16 M, fp32 P
    #pragma unroll
    for (int ii = 0; ii < 8; ii++) {
        int n = m0 + ty * 8 + ii;
        float pvals[8];
        uint32_t hh[4];
        #pragma unroll
        for (int q = 0; q < 4; q++) {
            uint32_t hp = 0;
            #pragma unroll
            for (int s = 0; s < 2; s++) {
                int jj = q * 2 + s;
                int keg = ke0 + tx * 8 + jj;
                float h = tanhf(acc[ii][jj] + b1[keg]);
                float w = g_w[n * 16 + (keg >> 5)];
                float m = w * (1.0f - h * h);
                pvals[jj] = w * h;
                hp |= ((uint32_t)__half_as_ushort(__float2half_rn(m))) << (16 * s);
            }
            hh[q] = hp;
        }
        int base = n * 512 + ke0 + tx * 8;
        *(uint4*)&g_Mh[base] = make_uint4(hh[0], hh[1], hh[2], hh[3]);
        *(float4*)&g_P[base]     = make_float4(pvals[0], pvals[1], pvals[2], pvals[3]);
        *(float4*)&g_P[base + 4] = make_float4(pvals[4], pvals[5], pvals[6], pvals[7]);
    }
}

// ---------------- z-GEMM: out_z += P @ W2 (512x64) --------------------------
__global__ void __launch_bounds__(256)
k_zgemm(const float* __restrict__ W2, float* __restrict__ out_z) {
    __shared__ float Ps[32][128];
    __shared__ float Vs[32][68];
    int m0 = blockIdx.x * 128;
    int tid = threadIdx.x;
    int ty = tid >> 4, tx = tid & 15;

    float acc[8][4];
    #pragma unroll
    for (int i = 0; i < 8; i++)
        #pragma unroll
        for (int j = 0; j < 4; j++) acc[i][j] = 0.0f;

    for (int kt = 0; kt < 16; kt++) {
        __syncthreads();
        #pragma unroll
        for (int it = 0; it < 4; it++) {               // P tile 128x32
            int lin = tid + it * 256;
            int row = lin >> 3, c4 = lin & 7;
            float4 vv = *(const float4*)&g_P[(m0 + row) * 512 + kt * 32 + c4 * 4];
            Ps[c4 * 4 + 0][row] = vv.x;
            Ps[c4 * 4 + 1][row] = vv.y;
            Ps[c4 * 4 + 2][row] = vv.z;
            Ps[c4 * 4 + 3][row] = vv.w;
        }
        #pragma unroll
        for (int it = 0; it < 2; it++) {               // W2 tile 32x64
            int lin = tid + it * 256;
            int r = lin >> 4, c4 = lin & 15;
            *(float4*)&Vs[r][c4 * 4] = *(const float4*)&W2[(kt * 32 + r) * 64 + c4 * 4];
        }
        __syncthreads();
        #pragma unroll
        for (int kk = 0; kk < 32; kk++) {
            float a[8], b[4];
            *(float4*)&a[0] = *(const float4*)&Ps[kk][ty * 8];
            *(float4*)&a[4] = *(const float4*)&Ps[kk][ty * 8 + 4];
            *(float4*)&b[0] = *(const float4*)&Vs[kk][tx * 4];
            #pragma unroll
            for (int i = 0; i < 8; i++)
                #pragma unroll
                for (int j = 0; j < 4; j++) acc[i][j] += a[i] * b[j];
        }
    }

    #pragma unroll
    for (int ii = 0; ii < 8; ii++) {
        int n = m0 + ty * 8 + ii;
        float4* p = (float4*)&out_z[n * 64 + tx * 4];
        float4 cur = *p;
        cur.x += acc[ii][0]; cur.y += acc[ii][1];
        cur.z += acc[ii][2]; cur.w += acc[ii][3];
        *p = cur;
    }
}

// ---------------- jac GEMM via mma.sync fp16 single pass --------------------
// out_j(32768x4096) = I + fp16(M)(32768x512) @ fp16(B)(512x4096)
// CTA tile 128(M) x 256(N), 8 warps (2m x 4n), warp tile 64x64.
// K chunks of 64, double-buffered cp.async, SW128-swizzled smem for ldmatrix.
// Stage layout: Ah 16K | Bh 32K = 48KB; 2 stages = 96KB.
#define J_TM 128
#define J_TN 256
#define J_KB 64
#define J_NKT 8
#define J_ST_SZ 49152
#define J_SMEM (2 * J_ST_SZ)

__device__ __forceinline__ void j_issue(uint32_t stage, int m0, int c0,
                                        int kt, int tid) {
    const char* pMh = (const char*)g_Mh;
    const char* pBh = (const char*)g_Bh;
    #pragma unroll
    for (int i = 0; i < 4; i++) {                  // A: 128 rows x 8 x 16B
        int lin = tid + i * 256;
        int r = lin >> 3, c = lin & 7;
        uint32_t off = r * 128 + c * 16;
        uint32_t sw = off ^ ((off >> 3) & 0x70);
        size_t go = ((size_t)(m0 + r) * 512 + kt * J_KB + c * 8) * 2;
        CPA16(stage + sw, pMh + go);
    }
    #pragma unroll
    for (int i = 0; i < 8; i++) {                  // B: 256 rows x 8 x 16B
        int lin = tid + i * 256;
        int r = lin >> 3, c = lin & 7;
        uint32_t off = r * 128 + c * 16;
        uint32_t sw = off ^ ((off >> 3) & 0x70);
        size_t go = ((size_t)(c0 + r) * 512 + kt * J_KB + c * 8) * 2;
        CPA16(stage + 16384 + sw, pBh + go);
    }
    asm volatile("cp.async.commit_group;" ::: "memory");
}

__global__ void __launch_bounds__(256, 1)
k_jac_mma(float* __restrict__ out_j) {
    extern __shared__ char smem[];
    const uint32_t sb = smem_u32(smem);
    const int tid  = threadIdx.x;
    const int lane = tid & 31;
    const int wid  = tid >> 5;
    const int wm   = wid >> 2;      // 0..1
    const int wn   = wid & 3;       // 0..3
    const int c0 = blockIdx.x * J_TN;
    const int m0 = blockIdx.y * J_TM;

    // ldmatrix per-thread address components
    const int a_row = wm * 64 + (lane & 15);
    const int a_t   = (a_row & 7) << 4;
    const int a_kl  = (lane >> 4) * 16;            // bytes
    const uint32_t a_base = (uint32_t)a_row * 128;
    const int b_row = wn * 64 + ((lane & 16) >> 1) + (lane & 7);
    const int b_t   = (b_row & 7) << 4;
    const int b_kl  = (lane & 8) * 2;              // bytes
    const uint32_t b_base = (uint32_t)b_row * 128;

    float acc[4][8][4];
    #pragma unroll
    for (int mt = 0; mt < 4; mt++)
        #pragma unroll
        for (int nt = 0; nt < 8; nt++)
            #pragma unroll
            for (int q = 0; q < 4; q++) acc[mt][nt][q] = 0.0f;

    j_issue(sb,           m0, c0, 0, tid);
    j_issue(sb + J_ST_SZ, m0, c0, 1, tid);

    for (int kt = 0; kt < J_NKT; kt++) {
        if (kt < J_NKT - 1)
            asm volatile("cp.async.wait_group 1;" ::: "memory");
        else
            asm volatile("cp.async.wait_group 0;" ::: "memory");
        __syncthreads();

        const uint32_t st = sb + (kt & 1) * J_ST_SZ;
        const uint32_t sAh = st;
        const uint32_t sBh = st + 16384;

        #pragma unroll
        for (int kk = 0; kk < 4; kk++) {
            const uint32_t akc = (uint32_t)((kk * 32 + a_kl) ^ a_t);
            const uint32_t bkc = (uint32_t)((kk * 32 + b_kl) ^ b_t);
            uint32_t Ah[4][4], Bx[4][4];
            #pragma unroll
            for (int mt = 0; mt < 4; mt++)
                ldsm4(Ah[mt], sAh + a_base + mt * 2048 + akc);
            #pragma unroll
            for (int nt = 0; nt < 4; nt++)
                ldsm4(Bx[nt], sBh + b_base + nt * 2048 + bkc);
            #pragma unroll
            for (int mt = 0; mt < 4; mt++)
                #pragma unroll
                for (int nt = 0; nt < 4; nt++) {
                    mma16816(acc[mt][nt * 2],     Ah[mt], Bx[nt][0], Bx[nt][1]);
                    mma16816(acc[mt][nt * 2 + 1], Ah[mt], Bx[nt][2], Bx[nt][3]);
                }
        }
        __syncthreads();
        if (kt + 2 < J_NKT)
            j_issue(sb + (kt & 1) * J_ST_SZ, m0, c0, kt + 2, tid);
    }

    // epilogue: identity on columns with c % 65 == 0 (independent of row)
    #pragma unroll
    for (int mt = 0; mt < 4; mt++) {
        size_t r0 = (size_t)m0 + wm * 64 + mt * 16 + (lane >> 2);
        #pragma unroll
        for (int nt = 0; nt < 8; nt++) {
            int c = c0 + wn * 64 + nt * 8 + 2 * (lane & 3);
            float add0 = ((c % 65) == 0) ? 1.0f : 0.0f;
            float add1 = (((c + 1) % 65) == 0) ? 1.0f : 0.0f;
            float2 v0 = make_float2(acc[mt][nt][0] + add0, acc[mt][nt][1] + add1);
            float2 v1 = make_float2(acc[mt][nt][2] + add0, acc[mt][nt][3] + add1);
            *(float2*)&out_j[r0 * 4096 + c]       = v0;
            *(float2*)&out_j[(r0 + 8) * 4096 + c] = v1;
        }
    }
}

// ---------------- launch ----------------------------------------------------
extern "C" void kernel_launch(void* const* d_in, const int* in_sizes, int n_in,
                              void* d_out, int out_size) {
    const float* x    = (const float*)d_in[0];
    const float* y    = (const float*)d_in[1];
    const float* W1   = (const float*)d_in[2];
    const float* b1   = (const float*)d_in[3];
    const float* W2   = (const float*)d_in[4];
    const float* b2   = (const float*)d_in[5];
    const float* Wb1  = (const float*)d_in[6];
    const float* bb1  = (const float*)d_in[7];
    const float* Wb2  = (const float*)d_in[8];
    const float* bb2  = (const float*)d_in[9];
    const float* Wc1  = (const float*)d_in[10];
    const float* bc1  = (const float*)d_in[11];
    const float* Wc2  = (const float*)d_in[12];
    const float* bc2  = (const float*)d_in[13];
    const float* mean = (const float*)d_in[14];
    const float* var  = (const float*)d_in[15];

    float* out   = (float*)d_out;
    float* out_z = out;                       // N*64
    float* out_j = out + (size_t)NN * NX;     // N*4096

    cudaFuncSetAttribute(k_jac_mma, cudaFuncAttributeMaxDynamicSharedMemorySize,
                         J_SMEM);

    k_prep_w1t<<<128, 256>>>(W1);
    k_prep_Bt<<<8192, 256>>>(W1, W2);
    k_branch<<<NN / 8, 256>>>(x, y, b2, Wb1, bb1, Wb2, bb2,
                              Wc1, bc1, Wc2, bc2, mean, var, out_z);
    k_hidden<<<dim3(4, NN / 128), 256>>>(x, b1);
    k_zgemm<<<NN / 128, 256>>>(W2, out_z);
    k_jac_mma<<<dim3(OUTC / J_TN, NN / J_TM), 256, J_SMEM>>>(out_j);
}

// round 10
// speedup vs baseline: 6.2068x; 1.1205x over previous
#include <cuda_runtime.h>
#include <cuda_fp16.h>
#include <math.h>
#include <stdint.h>

#define NN   32768
#define NX   64
#define KKK  16
#define EE   32
#define KE   512      // K*E
#define DYY  32
#define OUTC 4096     // NX*NX

// ---------------- scratch (device globals: no runtime allocation) -----------
__device__ __half g_Mh [NN * KE];   // 32 MB: fp16(w*(1-h^2))
__device__ __half g_Ph [NN * KE];   // 32 MB: fp16(w*h)
__device__ float  g_w  [NN * KKK];  //  2 MB: softplus branch weights
__device__ __half g_Bh [OUTC * KE]; //  4 MB: fp16(B^T[c][ke])
__device__ float  g_W1t[NX * KE];   // 128KB: W1t[i, ke] = W1[k,i,e]
__device__ __half g_W2t[NX * KE];   //  64KB: fp16(W2^T[o][ke])

// ================= PTX helpers (base sm_103 features only) ===================
__device__ __forceinline__ uint32_t smem_u32(const void* p) {
    uint32_t a;
    asm("{ .reg .u64 t; cvta.to.shared.u64 t, %1; cvt.u32.u64 %0, t; }"
        : "=r"(a) : "l"(p));
    return a;
}

#define CPA16(dst, src) \
    asm volatile("cp.async.cg.shared.global [%0], [%1], 16;" \
                 :: "r"((uint32_t)(dst)), "l"(src))

__device__ __forceinline__ void ldsm4(uint32_t* r, uint32_t addr) {
    asm volatile("ldmatrix.sync.aligned.m8n8.x4.shared.b16 {%0,%1,%2,%3}, [%4];"
                 : "=r"(r[0]), "=r"(r[1]), "=r"(r[2]), "=r"(r[3]) : "r"(addr));
}

__device__ __forceinline__ void mma16816(float* c, const uint32_t* a,
                                         uint32_t b0, uint32_t b1) {
    asm volatile(
        "mma.sync.aligned.m16n8k16.row.col.f32.f16.f16.f32 "
        "{%0,%1,%2,%3}, {%4,%5,%6,%7}, {%8,%9}, {%0,%1,%2,%3};"
        : "+f"(c[0]), "+f"(c[1]), "+f"(c[2]), "+f"(c[3])
        : "r"(a[0]), "r"(a[1]), "r"(a[2]), "r"(a[3]), "r"(b0), "r"(b1));
}

// ---------------- prep kernels ----------------------------------------------
// small transposes: W1t (fp32) and W2t (fp16)
__global__ void k_prep_small(const float* __restrict__ W1,
                             const float* __restrict__ W2) {
    int idx = blockIdx.x * 256 + threadIdx.x;          // < 64*512
    int i  = idx >> 9;
    int ke = idx & 511;
    int k = ke >> 5, e = ke & 31;
    g_W1t[idx] = W1[(k << 11) + (i << 5) + e];
    g_W2t[idx] = __float2half_rn(W2[(ke << 6) + i]);   // i plays role of o
}

// B^T[c][ke] = W2[k,e,o] * W1[k,i,e], c = o*64+i  (single fp16)
__global__ void k_prep_Bt(const float* __restrict__ W1,
                          const float* __restrict__ W2) {
    int idx = blockIdx.x * 256 + threadIdx.x;          // < 4096*512
    int c  = idx >> 9;
    int ke = idx & 511;
    int o = c >> 6, i = c & 63;
    int k = ke >> 5, e = ke & 31;
    float v = W2[(ke << 6) + o] * W1[(k << 11) + (i << 5) + e];
    g_Bh[idx] = __float2half_rn(v);
}

// ---------------- branch / bias / z0 (one warp per row) ---------------------
__global__ void __launch_bounds__(256)
k_branch(const float* __restrict__ x,   const float* __restrict__ y,
         const float* __restrict__ b2,
         const float* __restrict__ Wb1, const float* __restrict__ bb1,
         const float* __restrict__ Wb2, const float* __restrict__ bb2,
         const float* __restrict__ Wc1, const float* __restrict__ bc1,
         const float* __restrict__ Wc2, const float* __restrict__ bc2,
         const float* __restrict__ mean, const float* __restrict__ var,
         float* __restrict__ out_z) {
    __shared__ float sh[8 * 128];
    int warp = threadIdx.x >> 5;
    int lane = threadIdx.x & 31;
    int n = blockIdx.x * 8 + warp;

    float* yn = sh + warp * 128;   // 32
    float* t1 = yn + 32;           // 64
    float* t2 = yn + 96;           // 16
    float* wk = yn + 112;          // 16

    float v = (y[n * DYY + lane] - mean[lane]) * rsqrtf(var[lane]);
    yn[lane] = fminf(10.0f, fmaxf(-10.0f, v));
    __syncwarp();

    #pragma unroll
    for (int h = 0; h < 2; h++) {
        int j = lane + 32 * h;
        float s = bb1[j];
        #pragma unroll
        for (int d = 0; d < 32; d++) s += yn[d] * Wb1[d * 64 + j];
        t1[j] = fmaxf(s, 0.0f);
    }
    __syncwarp();

    if (lane < 16) {
        float s = bb2[lane];
        #pragma unroll
        for (int j = 0; j < 64; j++) s += t1[j] * Wb2[j * 16 + lane];
        float w = fmaxf(s, 0.0f) + log1pf(expf(-fabsf(s)));
        wk[lane] = w;
        g_w[n * 16 + lane] = w;
        float s2 = bc1[lane];
        #pragma unroll
        for (int d = 0; d < 32; d++) s2 += yn[d] * Wc1[d * 16 + lane];
        t2[lane] = fmaxf(s2, 0.0f);
    }
    __syncwarp();

    #pragma unroll
    for (int h = 0; h < 2; h++) {
        int o = lane + 32 * h;
        float s = x[n * 64 + o] + bc2[o];
        #pragma unroll
        for (int d = 0; d < 16; d++) s += t2[d] * Wc2[d * 64 + o];
        #pragma unroll
        for (int k = 0; k < 16; k++) s += wk[k] * b2[k * 64 + o];
        out_z[n * 64 + o] = s;
    }
}

// ---------------- h-GEMM: hpre = X @ W1t (+b1), tanh -> Mh, Ph --------------
__global__ void __launch_bounds__(256, 2)
k_hidden(const float* __restrict__ x, const float* __restrict__ b1) {
    __shared__ float Xs[16][128];      // [k][m]
    __shared__ float Ws[16][132];      // [k][ke_local]
    int ke0 = blockIdx.x * 128;
    int m0  = blockIdx.y * 128;
    int tid = threadIdx.x;
    int ty = tid >> 4, tx = tid & 15;

    float acc[8][8];
    #pragma unroll
    for (int i = 0; i < 8; i++)
        #pragma unroll
        for (int j = 0; j < 8; j++) acc[i][j] = 0.0f;

    for (int kt = 0; kt < 4; kt++) {
        __syncthreads();
        #pragma unroll
        for (int it = 0; it < 2; it++) {               // X tile 128x16
            int lin = tid + it * 256;
            int row = lin >> 2, c4 = lin & 3;
            float4 vv = *(const float4*)&x[(m0 + row) * 64 + kt * 16 + c4 * 4];
            Xs[c4 * 4 + 0][row] = vv.x;
            Xs[c4 * 4 + 1][row] = vv.y;
            Xs[c4 * 4 + 2][row] = vv.z;
            Xs[c4 * 4 + 3][row] = vv.w;
        }
        #pragma unroll
        for (int it = 0; it < 2; it++) {               // W1t tile 16x128
            int lin = tid + it * 256;
            int r = lin >> 5, c4 = lin & 31;
            float4 vv = *(const float4*)&g_W1t[(kt * 16 + r) * 512 + ke0 + c4 * 4];
            *(float4*)&Ws[r][c4 * 4] = vv;
        }
        __syncthreads();
        #pragma unroll
        for (int kk = 0; kk < 16; kk++) {
            float a[8], b[8];
            *(float4*)&a[0] = *(const float4*)&Xs[kk][ty * 8];
            *(float4*)&a[4] = *(const float4*)&Xs[kk][ty * 8 + 4];
            *(float4*)&b[0] = *(const float4*)&Ws[kk][tx * 8];
            *(float4*)&b[4] = *(const float4*)&Ws[kk][tx * 8 + 4];
            #pragma unroll
            for (int i = 0; i < 8; i++)
                #pragma unroll
                for (int j = 0; j < 8; j++) acc[i][j] += a[i] * b[j];
        }
    }

    // epilogue: tanh, weight, fp16 M and fp16 P
    #pragma unroll
    for (int ii = 0; ii < 8; ii++) {
        int n = m0 + ty * 8 + ii;
        uint32_t hh[4], pp[4];
        #pragma unroll
        for (int q = 0; q < 4; q++) {
            uint32_t hp = 0, pq = 0;
            #pragma unroll
            for (int s = 0; s < 2; s++) {
                int jj = q * 2 + s;
                int keg = ke0 + tx * 8 + jj;
                float h = tanhf(acc[ii][jj] + b1[keg]);
                float w = g_w[n * 16 + (keg >> 5)];
                float m = w * (1.0f - h * h);
                float p = w * h;
                hp |= ((uint32_t)__half_as_ushort(__float2half_rn(m))) << (16 * s);
                pq |= ((uint32_t)__half_as_ushort(__float2half_rn(p))) << (16 * s);
            }
            hh[q] = hp; pp[q] = pq;
        }
        int base = n * 512 + ke0 + tx * 8;
        *(uint4*)&g_Mh[base] = make_uint4(hh[0], hh[1], hh[2], hh[3]);
        *(uint4*)&g_Ph[base] = make_uint4(pp[0], pp[1], pp[2], pp[3]);
    }
}

// ---------------- z-GEMM via mma: out_z += fp16(P) @ fp16(W2) ---------------
// CTA: 256 rows x 64 cols, 8 warps (warp tile 32x64). Full W2^T resident in
// smem (8 K-chunks x [64 rows x 128B], SW128-swizzled). A double-buffered.
// smem: W2 64KB | A stage0 32KB | A stage1 32KB = 128KB.
#define Z_ROWS 256
#define Z_A_SZ 32768
#define Z_SMEM (65536 + 2 * Z_A_SZ)

__device__ __forceinline__ void z_issue_a(uint32_t stage, int m0, int kt, int tid) {
    const char* pPh = (const char*)g_Ph;
    #pragma unroll
    for (int i = 0; i < 8; i++) {                  // 256 rows x 8 x 16B
        int lin = tid + i * 256;
        int r = lin >> 3, c = lin & 7;
        uint32_t off = r * 128 + c * 16;
        uint32_t sw = off ^ ((off >> 3) & 0x70);
        size_t go = ((size_t)(m0 + r) * 512 + kt * 64 + c * 8) * 2;
        CPA16(stage + sw, pPh + go);
    }
    asm volatile("cp.async.commit_group;" ::: "memory");
}

__global__ void __launch_bounds__(256, 1)
k_z_mma(float* __restrict__ out_z) {
    extern __shared__ char smem[];
    const uint32_t sb = smem_u32(smem);
    const int tid  = threadIdx.x;
    const int lane = tid & 31;
    const int wid  = tid >> 5;       // warp 0..7 -> rows wid*32..+32
    const int m0 = blockIdx.x * Z_ROWS;

    // --- load full W2^T into smem (8 chunks of [64 rows][128B]) ---
    {
        const char* pW2 = (const char*)g_W2t;
        #pragma unroll
        for (int i = 0; i < 16; i++) {             // 4096 x 16B
            int lin = tid + i * 256;
            int kt = lin >> 9, rem = lin & 511;
            int r = rem >> 3, c = rem & 7;
            uint32_t off = r * 128 + c * 16;
            uint32_t sw = off ^ ((off >> 3) & 0x70);
            size_t go = ((size_t)r * 512 + kt * 64 + c * 8) * 2;
            CPA16(sb + kt * 8192 + sw, pW2 + go);
        }
    }
    z_issue_a(sb + 65536, m0, 0, tid);             // group also holds W2
    z_issue_a(sb + 65536 + Z_A_SZ, m0, 1, tid);

    // per-thread ldmatrix address components
    const int a_row = wid * 32 + (lane & 15);
    const int a_t   = (a_row & 7) << 4;
    const int a_kl  = (lane >> 4) * 16;
    const uint32_t a_base = (uint32_t)a_row * 128;
    const int b_row = ((lane & 16) >> 1) + (lane & 7);
    const int b_t   = (b_row & 7) << 4;
    const int b_kl  = (lane & 8) * 2;
    const uint32_t b_base = (uint32_t)b_row * 128;

    float acc[2][8][4];
    #pragma unroll
    for (int mt = 0; mt < 2; mt++)
        #pragma unroll
        for (int nt = 0; nt < 8; nt++)
            #pragma unroll
            for (int q = 0; q < 4; q++) acc[mt][nt][q] = 0.0f;

    for (int kt = 0; kt < 8; kt++) {
        if (kt < 7)
            asm volatile("cp.async.wait_group 1;" ::: "memory");
        else
            asm volatile("cp.async.wait_group 0;" ::: "memory");
        __syncthreads();

        const uint32_t sA = sb + 65536 + (kt & 1) * Z_A_SZ;
        const uint32_t sB = sb + kt * 8192;

        #pragma unroll
        for (int kk = 0; kk < 4; kk++) {
            const uint32_t akc = (uint32_t)((kk * 32 + a_kl) ^ a_t);
            const uint32_t bkc = (uint32_t)((kk * 32 + b_kl) ^ b_t);
            uint32_t Ah[2][4], Bx[4][4];
            #pragma unroll
            for (int mt = 0; mt < 2; mt++)
                ldsm4(Ah[mt], sA + a_base + mt * 2048 + akc);
            #pragma unroll
            for (int nt = 0; nt < 4; nt++)
                ldsm4(Bx[nt], sB + b_base + nt * 2048 + bkc);
            #pragma unroll
            for (int mt = 0; mt < 2; mt++)
                #pragma unroll
                for (int nt = 0; nt < 4; nt++) {
                    mma16816(acc[mt][nt * 2],     Ah[mt], Bx[nt][0], Bx[nt][1]);
                    mma16816(acc[mt][nt * 2 + 1], Ah[mt], Bx[nt][2], Bx[nt][3]);
                }
        }
        __syncthreads();
        if (kt + 2 < 8)
            z_issue_a(sb + 65536 + (kt & 1) * Z_A_SZ, m0, kt + 2, tid);
    }

    // epilogue: out_z += acc
    #pragma unroll
    for (int mt = 0; mt < 2; mt++) {
        size_t r0 = (size_t)m0 + wid * 32 + mt * 16 + (lane >> 2);
        #pragma unroll
        for (int nt = 0; nt < 8; nt++) {
            int c = nt * 8 + 2 * (lane & 3);
            float2* p0 = (float2*)&out_z[r0 * 64 + c];
            float2* p1 = (float2*)&out_z[(r0 + 8) * 64 + c];
            float2 v0 = *p0, v1 = *p1;
            v0.x += acc[mt][nt][0]; v0.y += acc[mt][nt][1];
            v1.x += acc[mt][nt][2]; v1.y += acc[mt][nt][3];
            *p0 = v0; *p1 = v1;
        }
    }
}

// ---------------- jac GEMM via mma.sync fp16 single pass --------------------
// out_j(32768x4096) = I + fp16(M)(32768x512) @ fp16(B)(512x4096)
// CTA tile 128(M) x 256(N), 8 warps (2m x 4n), warp tile 64x64.
// K chunks of 64, double-buffered cp.async, SW128-swizzled smem for ldmatrix.
// Stage layout: Ah 16K | Bh 32K = 48KB; 2 stages = 96KB.
#define J_TM 128
#define J_TN 256
#define J_KB 64
#define J_NKT 8
#define J_ST_SZ 49152
#define J_SMEM (2 * J_ST_SZ)

__device__ __forceinline__ void j_issue(uint32_t stage, int m0, int c0,
                                        int kt, int tid) {
    const char* pMh = (const char*)g_Mh;
    const char* pBh = (const char*)g_Bh;
    #pragma unroll
    for (int i = 0; i < 4; i++) {                  // A: 128 rows x 8 x 16B
        int lin = tid + i * 256;
        int r = lin >> 3, c = lin & 7;
        uint32_t off = r * 128 + c * 16;
        uint32_t sw = off ^ ((off >> 3) & 0x70);
        size_t go = ((size_t)(m0 + r) * 512 + kt * J_KB + c * 8) * 2;
        CPA16(stage + sw, pMh + go);
    }
    #pragma unroll
    for (int i = 0; i < 8; i++) {                  // B: 256 rows x 8 x 16B
        int lin = tid + i * 256;
        int r = lin >> 3, c = lin & 7;
        uint32_t off = r * 128 + c * 16;
        uint32_t sw = off ^ ((off >> 3) & 0x70);
        size_t go = ((size_t)(c0 + r) * 512 + kt * J_KB + c * 8) * 2;
        CPA16(stage + 16384 + sw, pBh + go);
    }
    asm volatile("cp.async.commit_group;" ::: "memory");
}

__global__ void __launch_bounds__(256, 1)
k_jac_mma(float* __restrict__ out_j) {
    extern __shared__ char smem[];
    const uint32_t sb = smem_u32(smem);
    const int tid  = threadIdx.x;
    const int lane = tid & 31;
    const int wid  = tid >> 5;
    const int wm   = wid >> 2;      // 0..1
    const int wn   = wid & 3;       // 0..3
    const int c0 = blockIdx.x * J_TN;
    const int m0 = blockIdx.y * J_TM;

    // ldmatrix per-thread address components
    const int a_row = wm * 64 + (lane & 15);
    const int a_t   = (a_row & 7) << 4;
    const int a_kl  = (lane >> 4) * 16;            // bytes
    const uint32_t a_base = (uint32_t)a_row * 128;
    const int b_row = wn * 64 + ((lane & 16) >> 1) + (lane & 7);
    const int b_t   = (b_row & 7) << 4;
    const int b_kl  = (lane & 8) * 2;              // bytes
    const uint32_t b_base = (uint32_t)b_row * 128;

    float acc[4][8][4];
    #pragma unroll
    for (int mt = 0; mt < 4; mt++)
        #pragma unroll
        for (int nt = 0; nt < 8; nt++)
            #pragma unroll
            for (int q = 0; q < 4; q++) acc[mt][nt][q] = 0.0f;

    j_issue(sb,           m0, c0, 0, tid);
    j_issue(sb + J_ST_SZ, m0, c0, 1, tid);

    for (int kt = 0; kt < J_NKT; kt++) {
        if (kt < J_NKT - 1)
            asm volatile("cp.async.wait_group 1;" ::: "memory");
        else
            asm volatile("cp.async.wait_group 0;" ::: "memory");
        __syncthreads();

        const uint32_t st = sb + (kt & 1) * J_ST_SZ;
        const uint32_t sAh = st;
        const uint32_t sBh = st + 16384;

        #pragma unroll
        for (int kk = 0; kk < 4; kk++) {
            const uint32_t akc = (uint32_t)((kk * 32 + a_kl) ^ a_t);
            const uint32_t bkc = (uint32_t)((kk * 32 + b_kl) ^ b_t);
            uint32_t Ah[4][4], Bx[4][4];
            #pragma unroll
            for (int mt = 0; mt < 4; mt++)
                ldsm4(Ah[mt], sAh + a_base + mt * 2048 + akc);
            #pragma unroll
            for (int nt = 0; nt < 4; nt++)
                ldsm4(Bx[nt], sBh + b_base + nt * 2048 + bkc);
            #pragma unroll
            for (int mt = 0; mt < 4; mt++)
                #pragma unroll
                for (int nt = 0; nt < 4; nt++) {
                    mma16816(acc[mt][nt * 2],     Ah[mt], Bx[nt][0], Bx[nt][1]);
                    mma16816(acc[mt][nt * 2 + 1], Ah[mt], Bx[nt][2], Bx[nt][3]);
                }
        }
        __syncthreads();
        if (kt + 2 < J_NKT)
            j_issue(sb + (kt & 1) * J_ST_SZ, m0, c0, kt + 2, tid);
    }

    // epilogue: identity on columns with c % 65 == 0 (independent of row)
    #pragma unroll
    for (int mt = 0; mt < 4; mt++) {
        size_t r0 = (size_t)m0 + wm * 64 + mt * 16 + (lane >> 2);
        #pragma unroll
        for (int nt = 0; nt < 8; nt++) {
            int c = c0 + wn * 64 + nt * 8 + 2 * (lane & 3);
            float add0 = ((c % 65) == 0) ? 1.0f : 0.0f;
            float add1 = (((c + 1) % 65) == 0) ? 1.0f : 0.0f;
            float2 v0 = make_float2(acc[mt][nt][0] + add0, acc[mt][nt][1] + add1);
            float2 v1 = make_float2(acc[mt][nt][2] + add0, acc[mt][nt][3] + add1);
            *(float2*)&out_j[r0 * 4096 + c]       = v0;
            *(float2*)&out_j[(r0 + 8) * 4096 + c] = v1;
        }
    }
}

// ---------------- launch ----------------------------------------------------
extern "C" void kernel_launch(void* const* d_in, const int* in_sizes, int n_in,
                              void* d_out, int out_size) {
    const float* x    = (const float*)d_in[0];
    const float* y    = (const float*)d_in[1];
    const float* W1   = (const float*)d_in[2];
    const float* b1   = (const float*)d_in[3];
    const float* W2   = (const float*)d_in[4];
    const float* b2   = (const float*)d_in[5];
    const float* Wb1  = (const float*)d_in[6];
    const float* bb1  = (const float*)d_in[7];
    const float* Wb2  = (const float*)d_in[8];
    const float* bb2  = (const float*)d_in[9];
    const float* Wc1  = (const float*)d_in[10];
    const float* bc1  = (const float*)d_in[11];
    const float* Wc2  = (const float*)d_in[12];
    const float* bc2  = (const float*)d_in[13];
    const float* mean = (const float*)d_in[14];
    const float* var  = (const float*)d_in[15];

    float* out   = (float*)d_out;
    float* out_z = out;                       // N*64
    float* out_j = out + (size_t)NN * NX;     // N*4096

    cudaFuncSetAttribute(k_jac_mma, cudaFuncAttributeMaxDynamicSharedMemorySize,
                         J_SMEM);
    cudaFuncSetAttribute(k_z_mma, cudaFuncAttributeMaxDynamicSharedMemorySize,
                         Z_SMEM);

    k_prep_small<<<128, 256>>>(W1, W2);
    k_prep_Bt<<<8192, 256>>>(W1, W2);
    k_branch<<<NN / 8, 256>>>(x, y, b2, Wb1, bb1, Wb2, bb2,
                              Wc1, bc1, Wc2, bc2, mean, var, out_z);
    k_hidden<<<dim3(4, NN / 128), 256>>>(x, b1);
    k_z_mma<<<NN / Z_ROWS, 256, Z_SMEM>>>(out_z);
    k_jac_mma<<<dim3(OUTC / J_TN, NN / J_TM), 256, J_SMEM>>>(out_j);
}

// round 14
// speedup vs baseline: 6.5900x; 1.0617x over previous
#include <cuda_runtime.h>
#include <cuda_fp16.h>
#include <math.h>
#include <stdint.h>

#define NN   32768
#define NX   64
#define KKK  16
#define EE   32
#define KE   512      // K*E
#define DYY  32
#define OUTC 4096     // NX*NX

// ---------------- scratch (device globals: no runtime allocation) -----------
__device__ __half g_Mh [NN * KE];   // 32 MB: fp16(w*(1-h^2))
__device__ __half g_xh [NN * NX];   //  4 MB: fp16(x)
__device__ float  g_w  [NN * KKK];  //  2 MB: softplus branch weights
__device__ __half g_Bh [OUTC * KE]; //  4 MB: fp16(B^T[c][ke])
__device__ __half g_w1r[KE * NX];   //  64KB: fp16(W1r[ke][i]) = W1[k,i,e]
__device__ __half g_W2t[NX * KE];   //  64KB: fp16(W2^T[o][ke])

// ================= PTX helpers (base sm_103 features only) ===================
__device__ __forceinline__ uint32_t smem_u32(const void* p) {
    uint32_t a;
    asm("{ .reg .u64 t; cvta.to.shared.u64 t, %1; cvt.u32.u64 %0, t; }"
        : "=r"(a) : "l"(p));
    return a;
}

#define CPA16(dst, src) \
    asm volatile("cp.async.cg.shared.global [%0], [%1], 16;" \
                 :: "r"((uint32_t)(dst)), "l"(src))

__device__ __forceinline__ void ldsm4(uint32_t* r, uint32_t addr) {
    asm volatile("ldmatrix.sync.aligned.m8n8.x4.shared.b16 {%0,%1,%2,%3}, [%4];"
                 : "=r"(r[0]), "=r"(r[1]), "=r"(r[2]), "=r"(r[3]) : "r"(addr));
}

__device__ __forceinline__ void mma16816(float* c, const uint32_t* a,
                                         uint32_t b0, uint32_t b1) {
    asm volatile(
        "mma.sync.aligned.m16n8k16.row.col.f32.f16.f16.f32 "
        "{%0,%1,%2,%3}, {%4,%5,%6,%7}, {%8,%9}, {%0,%1,%2,%3};"
        : "+f"(c[0]), "+f"(c[1]), "+f"(c[2]), "+f"(c[3])
        : "r"(a[0]), "r"(a[1]), "r"(a[2]), "r"(a[3]), "r"(b0), "r"(b1));
}

__device__ __forceinline__ uint32_t sw128(uint32_t off) {
    return off ^ ((off >> 3) & 0x70);
}

// ---------------- prep kernels ----------------------------------------------
// W1r fp16 [ke][i] and W2t fp16 [o][ke]
__global__ void k_prep_small(const float* __restrict__ W1,
                             const float* __restrict__ W2) {
    int idx = blockIdx.x * 256 + threadIdx.x;          // < 64*512
    int i  = idx >> 9;
    int ke = idx & 511;
    int k = ke >> 5, e = ke & 31;
    g_w1r[ke * 64 + i] = __float2half_rn(W1[(k << 11) + (i << 5) + e]);
    g_W2t[idx] = __float2half_rn(W2[(ke << 6) + i]);   // i plays role of o
}

// B^T[c][ke] = W2[k,e,o] * W1[k,i,e], c = o*64+i  (single fp16)
__global__ void k_prep_Bt(const float* __restrict__ W1,
                          const float* __restrict__ W2) {
    int idx = blockIdx.x * 256 + threadIdx.x;          // < 4096*512
    int c  = idx >> 9;
    int ke = idx & 511;
    int o = c >> 6, i = c & 63;
    int k = ke >> 5, e = ke & 31;
    float v = W2[(ke << 6) + o] * W1[(k << 11) + (i << 5) + e];
    g_Bh[idx] = __float2half_rn(v);
}

// ---------------- branch / bias / z0 (one warp per row) ---------------------
__global__ void __launch_bounds__(256)
k_branch(const float* __restrict__ x,   const float* __restrict__ y,
         const float* __restrict__ b2,
         const float* __restrict__ Wb1, const float* __restrict__ bb1,
         const float* __restrict__ Wb2, const float* __restrict__ bb2,
         const float* __restrict__ Wc1, const float* __restrict__ bc1,
         const float* __restrict__ Wc2, const float* __restrict__ bc2,
         const float* __restrict__ mean, const float* __restrict__ var,
         float* __restrict__ out_z) {
    __shared__ float sh[8 * 128];
    int warp = threadIdx.x >> 5;
    int lane = threadIdx.x & 31;
    int n = blockIdx.x * 8 + warp;

    float* yn = sh + warp * 128;   // 32
    float* t1 = yn + 32;           // 64
    float* t2 = yn + 96;           // 16
    float* wk = yn + 112;          // 16

    float v = (y[n * DYY + lane] - mean[lane]) * rsqrtf(var[lane]);
    yn[lane] = fminf(10.0f, fmaxf(-10.0f, v));
    __syncwarp();

    #pragma unroll
    for (int h = 0; h < 2; h++) {
        int j = lane + 32 * h;
        float s = bb1[j];
        #pragma unroll
        for (int d = 0; d < 32; d++) s += yn[d] * Wb1[d * 64 + j];
        t1[j] = fmaxf(s, 0.0f);
    }
    __syncwarp();

    if (lane < 16) {
        float s = bb2[lane];
        #pragma unroll
        for (int j = 0; j < 64; j++) s += t1[j] * Wb2[j * 16 + lane];
        float w = fmaxf(s, 0.0f) + log1pf(expf(-fabsf(s)));
        wk[lane] = w;
        g_w[n * 16 + lane] = w;
        float s2 = bc1[lane];
        #pragma unroll
        for (int d = 0; d < 32; d++) s2 += yn[d] * Wc1[d * 16 + lane];
        t2[lane] = fmaxf(s2, 0.0f);
    }
    __syncwarp();

    #pragma unroll
    for (int h = 0; h < 2; h++) {
        int o = lane + 32 * h;
        float xv = x[n * 64 + o];
        g_xh[n * 64 + o] = __float2half_rn(xv);        // fp16 x for hidden
        float s = xv + bc2[o];
        #pragma unroll
        for (int d = 0; d < 16; d++) s += t2[d] * Wc2[d * 64 + o];
        #pragma unroll
        for (int k = 0; k < 16; k++) s += wk[k] * b2[k * 64 + o];
        out_z[n * 64 + o] = s;
    }
}

// ---------------- fused hidden + z kernel (no atomics, no smem overlay) -----
// One CTA owns 128 rows and loops over all 4 ke-blocks of 128:
//  pass1: hpre = Xh(128x64) @ W1r(128ke x 64)^T   (fp16 mma, fp32 accum)
//  epi:   h = tanh(hpre + b1); m = w(1-h^2) -> sM (flushed to g_Mh);
//         p = w*h -> sP
//  pass2: accz += P(128x128ke) @ W2t(64o x 128ke)^T   (register accum)
// After the loop: out_z[row] += accz (plain RMW, unique owner per element).
// SMEM: SX 16K | SW1 16K | SW2 16K | sM 32K | sP 32K | swt 8K | sb1 2K
#define H_SX   0
#define H_SW1  16384
#define H_SW2  32768
#define H_SM   49152
#define H_SP   81920
#define H_SWT  114688
#define H_SB1  122880
#define H_SMEM 124928

__global__ void __launch_bounds__(256)
k_hidden_f(const float* __restrict__ b1, float* __restrict__ out_z) {
    extern __shared__ char smem[];
    const uint32_t sb = smem_u32(smem);
    float* swt = (float*)(smem + H_SWT);
    float* sb1 = (float*)(smem + H_SB1);
    const int tid  = threadIdx.x;
    const int lane = tid & 31;
    const int wid  = tid >> 5;
    const int wm   = wid >> 2;        // 0..1
    const int wn   = wid & 3;         // 0..3
    const int m0 = blockIdx.x * 128;  // rows

    // --- persistent loads: X tile (cp.async), w tile, b1 (plain) ---
    {
        const char* pX = (const char*)g_xh;
        #pragma unroll
        for (int i = 0; i < 4; i++) {              // X: 128 rows x 8 x 16B
            int lin = tid + i * 256;
            int r = lin >> 3, c = lin & 7;
            CPA16(sb + H_SX + sw128(r * 128 + c * 16),
                  pX + (size_t)(m0 + r) * 128 + c * 16);
        }
        asm volatile("cp.async.commit_group;" ::: "memory");
    }
    #pragma unroll
    for (int i = 0; i < 8; i++) {
        int lin = tid + i * 256;                   // 2048 floats
        swt[lin] = g_w[(size_t)m0 * 16 + lin];
    }
    #pragma unroll
    for (int i = 0; i < 2; i++) sb1[tid + i * 256] = b1[tid + i * 256];

    // per-thread ldmatrix address components (pass 1)
    const int a_row = wm * 64 + (lane & 15);
    const int a_t   = (a_row & 7) << 4;
    const int a_kl  = (lane >> 4) * 16;
    const uint32_t a_base = (uint32_t)a_row * 128;
    const int b_row = wn * 32 + ((lane & 16) >> 1) + (lane & 7);
    const int b_t   = (b_row & 7) << 4;
    const int b_kl  = (lane & 8) * 2;
    const uint32_t b_base = (uint32_t)b_row * 128;
    const int a2_row = wid * 16 + (lane & 15);     // pass 2 A rows

    float accz[8][4];
    #pragma unroll
    for (int nt = 0; nt < 8; nt++)
        #pragma unroll
        for (int q = 0; q < 4; q++) accz[nt][q] = 0.0f;

    for (int ci = 0; ci < 4; ci++) {
        const int c0 = ci * 128;

        // --- load this ke-block's W1 (128x128B) and W2 (2 chunks 64x128B) ---
        {
            const char* pW1 = (const char*)g_w1r;
            const char* pW2 = (const char*)g_W2t;
            #pragma unroll
            for (int i = 0; i < 4; i++) {
                int lin = tid + i * 256;
                int r = lin >> 3, c = lin & 7;
                CPA16(sb + H_SW1 + sw128(r * 128 + c * 16),
                      pW1 + (size_t)(c0 + r) * 128 + c * 16);
            }
            #pragma unroll
            for (int i = 0; i < 4; i++) {
                int lin = tid + i * 256;
                int ch = lin >> 9, rem = lin & 511;
                int r = rem >> 3, c = rem & 7;
                CPA16(sb + H_SW2 + ch * 8192 + sw128(r * 128 + c * 16),
                      pW2 + (size_t)r * 1024 + (c0 + ch * 64 + c * 8) * 2);
            }
            asm volatile("cp.async.commit_group;" ::: "memory");
            asm volatile("cp.async.wait_group 0;" ::: "memory");
        }
        __syncthreads();

        // --- pass 1: hpre mma (warp tile 64 rows x 32 ke) ---
        float acc[4][4][4];
        #pragma unroll
        for (int mt = 0; mt < 4; mt++)
            #pragma unroll
            for (int nt = 0; nt < 4; nt++)
                #pragma unroll
                for (int q = 0; q < 4; q++) acc[mt][nt][q] = 0.0f;

        #pragma unroll
        for (int kk = 0; kk < 4; kk++) {
            const uint32_t akc = (uint32_t)((kk * 32 + a_kl) ^ a_t);
            const uint32_t bkc = (uint32_t)((kk * 32 + b_kl) ^ b_t);
            uint32_t Ah[4][4], Bx[2][4];
            #pragma unroll
            for (int mt = 0; mt < 4; mt++)
                ldsm4(Ah[mt], sb + H_SX + a_base + mt * 2048 + akc);
            #pragma unroll
            for (int n2 = 0; n2 < 2; n2++)
                ldsm4(Bx[n2], sb + H_SW1 + b_base + n2 * 2048 + bkc);
            #pragma unroll
            for (int mt = 0; mt < 4; mt++)
                #pragma unroll
                for (int n2 = 0; n2 < 2; n2++) {
                    mma16816(acc[mt][n2 * 2],     Ah[mt], Bx[n2][0], Bx[n2][1]);
                    mma16816(acc[mt][n2 * 2 + 1], Ah[mt], Bx[n2][2], Bx[n2][3]);
                }
        }

        // --- epilogue 1: tanh, m -> sM, p -> sP ---
        #pragma unroll
        for (int mt = 0; mt < 4; mt++) {
            #pragma unroll
            for (int qq = 0; qq < 2; qq++) {       // qq=0: rows r, qq=1: r+8
                int r_l = wm * 64 + mt * 16 + (lane >> 2) + qq * 8;
                #pragma unroll
                for (int nt = 0; nt < 4; nt++) {
                    int ke_l = wn * 32 + nt * 8 + 2 * (lane & 3);
                    float w = swt[r_l * 16 + ((c0 + ke_l) >> 5)];
                    float h0 = tanhf(acc[mt][nt][qq * 2]     + sb1[c0 + ke_l]);
                    float h1 = tanhf(acc[mt][nt][qq * 2 + 1] + sb1[c0 + ke_l + 1]);
                    __half2 mv = __floats2half2_rn(w * (1.0f - h0 * h0),
                                                   w * (1.0f - h1 * h1));
                    __half2 pv = __floats2half2_rn(w * h0, w * h1);
                    int ch = ke_l >> 6;
                    uint32_t off = sw128((uint32_t)r_l * 128 + (ke_l & 63) * 2);
                    *(__half2*)(smem + H_SM + ch * 16384 + off) = mv;
                    *(__half2*)(smem + H_SP + ch * 16384 + off) = pv;
                }
            }
        }
        __syncthreads();

        // --- flush M tile to g_Mh (coalesced uint4) ---
        #pragma unroll
        for (int i = 0; i < 8; i++) {
            int lin = tid + i * 256;               // 2048 uint4
            int r = lin >> 4, c16 = lin & 15;
            int ch = c16 >> 3;
            uint32_t soff = sw128((uint32_t)r * 128 + (c16 & 7) * 16);
            uint4 v = *(uint4*)(smem + H_SM + ch * 16384 + soff);
            *(uint4*)((char*)g_Mh + (size_t)(m0 + r) * 1024
                      + (c0 + c16 * 8) * 2) = v;
        }

        // --- pass 2: accz += P @ W2t (warp = 16 rows x 64 cols) ---
        #pragma unroll
        for (int ck = 0; ck < 8; ck++) {
            int ch = ck >> 2, kk = ck & 3;
            uint32_t aoff = sw128((uint32_t)a2_row * 128 + kk * 32 + a_kl);
            uint32_t Ah2[4];
            ldsm4(Ah2, sb + H_SP + ch * 16384 + aoff);
            #pragma unroll
            for (int n2 = 0; n2 < 4; n2++) {       // 4 x 16 o-rows
                int brow = n2 * 16 + ((lane & 16) >> 1) + (lane & 7);
                uint32_t boff = sw128((uint32_t)brow * 128 + kk * 32 + b_kl);
                uint32_t Bx2[4];
                ldsm4(Bx2, sb + H_SW2 + ch * 8192 + boff);
                mma16816(accz[n2 * 2],     Ah2, Bx2[0], Bx2[1]);
                mma16816(accz[n2 * 2 + 1], Ah2, Bx2[2], Bx2[3]);
            }
        }
        __syncthreads();   // all reads done before next iter overwrites smem
    }

    // --- final: out_z += accz (unique owner per element, plain RMW) ---
    #pragma unroll
    for (int nt = 0; nt < 8; nt++) {
        int o = nt * 8 + 2 * (lane & 3);
        size_t r = (size_t)m0 + wid * 16 + (lane >> 2);
        float2* p0 = (float2*)&out_z[r * 64 + o];
        float2* p1 = (float2*)&out_z[(r + 8) * 64 + o];
        float2 v0 = *p0, v1 = *p1;
        v0.x += accz[nt][0]; v0.y += accz[nt][1];
        v1.x += accz[nt][2]; v1.y += accz[nt][3];
        *p0 = v0; *p1 = v1;
    }
}

// ---------------- jac GEMM via mma.sync fp16 single pass --------------------
// out_j(32768x4096) = I + fp16(M)(32768x512) @ fp16(B)(512x4096)
// CTA tile 128(M) x 256(N), 8 warps (2m x 4n), warp tile 64x64.
// K chunks of 64, double-buffered cp.async, SW128-swizzled smem for ldmatrix.
// Stage layout: Ah 16K | Bh 32K = 48KB; 2 stages = 96KB.
#define J_TM 128
#define J_TN 256
#define J_KB 64
#define J_NKT 8
#define J_ST_SZ 49152
#define J_SMEM (2 * J_ST_SZ)

__device__ __forceinline__ void j_issue(uint32_t stage, int m0, int c0,
                                        int kt, int tid) {
    const char* pMh = (const char*)g_Mh;
    const char* pBh = (const char*)g_Bh;
    #pragma unroll
    for (int i = 0; i < 4; i++) {                  // A: 128 rows x 8 x 16B
        int lin = tid + i * 256;
        int r = lin >> 3, c = lin & 7;
        uint32_t off = r * 128 + c * 16;
        uint32_t sw = off ^ ((off >> 3) & 0x70);
        size_t go = ((size_t)(m0 + r) * 512 + kt * J_KB + c * 8) * 2;
        CPA16(stage + sw, pMh + go);
    }
    #pragma unroll
    for (int i = 0; i < 8; i++) {                  // B: 256 rows x 8 x 16B
        int lin = tid + i * 256;
        int r = lin >> 3, c = lin & 7;
        uint32_t off = r * 128 + c * 16;
        uint32_t sw = off ^ ((off >> 3) & 0x70);
        size_t go = ((size_t)(c0 + r) * 512 + kt * J_KB + c * 8) * 2;
        CPA16(stage + 16384 + sw, pBh + go);
    }
    asm volatile("cp.async.commit_group;" ::: "memory");
}

__global__ void __launch_bounds__(256, 1)
k_jac_mma(float* __restrict__ out_j) {
    extern __shared__ char smem[];
    const uint32_t sb = smem_u32(smem);
    const int tid  = threadIdx.x;
    const int lane = tid & 31;
    const int wid  = tid >> 5;
    const int wm   = wid >> 2;      // 0..1
    const int wn   = wid & 3;       // 0..3
    const int c0 = blockIdx.x * J_TN;
    const int m0 = blockIdx.y * J_TM;

    // ldmatrix per-thread address components
    const int a_row = wm * 64 + (lane & 15);
    const int a_t   = (a_row & 7) << 4;
    const int a_kl  = (lane >> 4) * 16;            // bytes
    const uint32_t a_base = (uint32_t)a_row * 128;
    const int b_row = wn * 64 + ((lane & 16) >> 1) + (lane & 7);
    const int b_t   = (b_row & 7) << 4;
    const int b_kl  = (lane & 8) * 2;              // bytes
    const uint32_t b_base = (uint32_t)b_row * 128;

    float acc[4][8][4];
    #pragma unroll
    for (int mt = 0; mt < 4; mt++)
        #pragma unroll
        for (int nt = 0; nt < 8; nt++)
            #pragma unroll
            for (int q = 0; q < 4; q++) acc[mt][nt][q] = 0.0f;

    j_issue(sb,           m0, c0, 0, tid);
    j_issue(sb + J_ST_SZ, m0, c0, 1, tid);

    for (int kt = 0; kt < J_NKT; kt++) {
        if (kt < J_NKT - 1)
            asm volatile("cp.async.wait_group 1;" ::: "memory");
        else
            asm volatile("cp.async.wait_group 0;" ::: "memory");
        __syncthreads();

        const uint32_t st = sb + (kt & 1) * J_ST_SZ;
        const uint32_t sAh = st;
        const uint32_t sBh = st + 16384;

        #pragma unroll
        for (int kk = 0; kk < 4; kk++) {
            const uint32_t akc = (uint32_t)((kk * 32 + a_kl) ^ a_t);
            const uint32_t bkc = (uint32_t)((kk * 32 + b_kl) ^ b_t);
            uint32_t Ah[4][4], Bx[4][4];
            #pragma unroll
            for (int mt = 0; mt < 4; mt++)
                ldsm4(Ah[mt], sAh + a_base + mt * 2048 + akc);
            #pragma unroll
            for (int nt = 0; nt < 4; nt++)
                ldsm4(Bx[nt], sBh + b_base + nt * 2048 + bkc);
            #pragma unroll
            for (int mt = 0; mt < 4; mt++)
                #pragma unroll
                for (int nt = 0; nt < 4; nt++) {
                    mma16816(acc[mt][nt * 2],     Ah[mt], Bx[nt][0], Bx[nt][1]);
                    mma16816(acc[mt][nt * 2 + 1], Ah[mt], Bx[nt][2], Bx[nt][3]);
                }
        }
        __syncthreads();
        if (kt + 2 < J_NKT)
            j_issue(sb + (kt & 1) * J_ST_SZ, m0, c0, kt + 2, tid);
    }

    // epilogue: identity on columns with c % 65 == 0 (independent of row)
    #pragma unroll
    for (int mt = 0; mt < 4; mt++) {
        size_t r0 = (size_t)m0 + wm * 64 + mt * 16 + (lane >> 2);
        #pragma unroll
        for (int nt = 0; nt < 8; nt++) {
            int c = c0 + wn * 64 + nt * 8 + 2 * (lane & 3);
            float add0 = ((c % 65) == 0) ? 1.0f : 0.0f;
            float add1 = (((c + 1) % 65) == 0) ? 1.0f : 0.0f;
            float2 v0 = make_float2(acc[mt][nt][0] + add0, acc[mt][nt][1] + add1);
            float2 v1 = make_float2(acc[mt][nt][2] + add0, acc[mt][nt][3] + add1);
            *(float2*)&out_j[r0 * 4096 + c]       = v0;
            *(float2*)&out_j[(r0 + 8) * 4096 + c] = v1;
        }
    }
}

// ---------------- launch ----------------------------------------------------
extern "C" void kernel_launch(void* const* d_in, const int* in_sizes, int n_in,
                              void* d_out, int out_size) {
    const float* x    = (const float*)d_in[0];
    const float* y    = (const float*)d_in[1];
    const float* W1   = (const float*)d_in[2];
    const float* b1   = (const float*)d_in[3];
    const float* W2   = (const float*)d_in[4];
    const float* b2   = (const float*)d_in[5];
    const float* Wb1  = (const float*)d_in[6];
    const float* bb1  = (const float*)d_in[7];
    const float* Wb2  = (const float*)d_in[8];
    const float* bb2  = (const float*)d_in[9];
    const float* Wc1  = (const float*)d_in[10];
    const float* bc1  = (const float*)d_in[11];
    const float* Wc2  = (const float*)d_in[12];
    const float* bc2  = (const float*)d_in[13];
    const float* mean = (const float*)d_in[14];
    const float* var  = (const float*)d_in[15];

    float* out   = (float*)d_out;
    float* out_z = out;                       // N*64
    float* out_j = out + (size_t)NN * NX;     // N*4096

    cudaFuncSetAttribute(k_jac_mma, cudaFuncAttributeMaxDynamicSharedMemorySize,
                         J_SMEM);
    cudaFuncSetAttribute(k_hidden_f, cudaFuncAttributeMaxDynamicSharedMemorySize,
                         H_SMEM);

    k_prep_small<<<128, 256>>>(W1, W2);
    k_prep_Bt<<<8192, 256>>>(W1, W2);
    k_branch<<<NN / 8, 256>>>(x, y, b2, Wb1, bb1, Wb2, bb2,
                              Wc1, bc1, Wc2, bc2, mean, var, out_z);
    k_hidden_f<<<NN / 128, 256, H_SMEM>>>(b1, out_z);
    k_jac_mma<<<dim3(OUTC / J_TN, NN / J_TM), 256, J_SMEM>>>(out_j);
}

// round 17
// speedup vs baseline: 7.4580x; 1.1317x over previous
#include <cuda_runtime.h>
#include <cuda_fp16.h>
#include <math.h>
#include <stdint.h>

#define NN   32768
#define NX   64
#define KKK  16
#define EE   32
#define KE   512      // K*E
#define DYY  32
#define OUTC 4096     // NX*NX

// ---------------- scratch (device globals: no runtime allocation) -----------
__device__ __half g_Mh [NN * KE];   // 32 MB: fp16(w*(1-h^2))
__device__ __half g_xh [NN * NX];   //  4 MB: fp16(x)
__device__ float  g_w  [NN * KKK];  //  2 MB: softplus branch weights
__device__ __half g_Bh [OUTC * KE]; //  4 MB: fp16(B^T[c][ke])
__device__ __half g_w1r[KE * NX];   //  64KB: fp16(W1r[ke][i]) = W1[k,i,e]
__device__ __half g_W2t[NX * KE];   //  64KB: fp16(W2^T[o][ke])

// ================= PTX helpers (base sm_103 features only) ===================
__device__ __forceinline__ uint32_t smem_u32(const void* p) {
    uint32_t a;
    asm("{ .reg .u64 t; cvta.to.shared.u64 t, %1; cvt.u32.u64 %0, t; }"
        : "=r"(a) : "l"(p));
    return a;
}

#define CPA16(dst, src) \
    asm volatile("cp.async.cg.shared.global [%0], [%1], 16;" \
                 :: "r"((uint32_t)(dst)), "l"(src))

__device__ __forceinline__ void ldsm4(uint32_t* r, uint32_t addr) {
    asm volatile("ldmatrix.sync.aligned.m8n8.x4.shared.b16 {%0,%1,%2,%3}, [%4];"
                 : "=r"(r[0]), "=r"(r[1]), "=r"(r[2]), "=r"(r[3]) : "r"(addr));
}

__device__ __forceinline__ void mma16816(float* c, const uint32_t* a,
                                         uint32_t b0, uint32_t b1) {
    asm volatile(
        "mma.sync.aligned.m16n8k16.row.col.f32.f16.f16.f32 "
        "{%0,%1,%2,%3}, {%4,%5,%6,%7}, {%8,%9}, {%0,%1,%2,%3};"
        : "+f"(c[0]), "+f"(c[1]), "+f"(c[2]), "+f"(c[3])
        : "r"(a[0]), "r"(a[1]), "r"(a[2]), "r"(a[3]), "r"(b0), "r"(b1));
}

__device__ __forceinline__ uint32_t sw128(uint32_t off) {
    return off ^ ((off >> 3) & 0x70);
}

// ---------------- prep kernels ----------------------------------------------
// W1r fp16 [ke][i] and W2t fp16 [o][ke]
__global__ void k_prep_small(const float* __restrict__ W1,
                             const float* __restrict__ W2) {
    int idx = blockIdx.x * 256 + threadIdx.x;          // < 64*512
    int i  = idx >> 9;
    int ke = idx & 511;
    int k = ke >> 5, e = ke & 31;
    g_w1r[ke * 64 + i] = __float2half_rn(W1[(k << 11) + (i << 5) + e]);
    g_W2t[idx] = __float2half_rn(W2[(ke << 6) + i]);   // i plays role of o
}

// B^T[c][ke] = W2[k,e,o] * W1[k,i,e], c = o*64+i  (single fp16)
__global__ void k_prep_Bt(const float* __restrict__ W1,
                          const float* __restrict__ W2) {
    int idx = blockIdx.x * 256 + threadIdx.x;          // < 4096*512
    int c  = idx >> 9;
    int ke = idx & 511;
    int o = c >> 6, i = c & 63;
    int k = ke >> 5, e = ke & 31;
    float v = W2[(ke << 6) + o] * W1[(k << 11) + (i << 5) + e];
    g_Bh[idx] = __float2half_rn(v);
}

// ---------------- branch / bias / z0 (one warp per row) ---------------------
__global__ void __launch_bounds__(256)
k_branch(const float* __restrict__ x,   const float* __restrict__ y,
         const float* __restrict__ b2,
         const float* __restrict__ Wb1, const float* __restrict__ bb1,
         const float* __restrict__ Wb2, const float* __restrict__ bb2,
         const float* __restrict__ Wc1, const float* __restrict__ bc1,
         const float* __restrict__ Wc2, const float* __restrict__ bc2,
         const float* __restrict__ mean, const float* __restrict__ var,
         float* __restrict__ out_z) {
    __shared__ float sh[8 * 128];
    int warp = threadIdx.x >> 5;
    int lane = threadIdx.x & 31;
    int n = blockIdx.x * 8 + warp;

    float* yn = sh + warp * 128;   // 32
    float* t1 = yn + 32;           // 64
    float* t2 = yn + 96;           // 16
    float* wk = yn + 112;          // 16

    float v = (y[n * DYY + lane] - mean[lane]) * rsqrtf(var[lane]);
    yn[lane] = fminf(10.0f, fmaxf(-10.0f, v));
    __syncwarp();

    #pragma unroll
    for (int h = 0; h < 2; h++) {
        int j = lane + 32 * h;
        float s = bb1[j];
        #pragma unroll
        for (int d = 0; d < 32; d++) s += yn[d] * Wb1[d * 64 + j];
        t1[j] = fmaxf(s, 0.0f);
    }
    __syncwarp();

    if (lane < 16) {
        float s = bb2[lane];
        #pragma unroll
        for (int j = 0; j < 64; j++) s += t1[j] * Wb2[j * 16 + lane];
        float w = fmaxf(s, 0.0f) + log1pf(expf(-fabsf(s)));
        wk[lane] = w;
        g_w[n * 16 + lane] = w;
        float s2 = bc1[lane];
        #pragma unroll
        for (int d = 0; d < 32; d++) s2 += yn[d] * Wc1[d * 16 + lane];
        t2[lane] = fmaxf(s2, 0.0f);
    }
    __syncwarp();

    #pragma unroll
    for (int h = 0; h < 2; h++) {
        int o = lane + 32 * h;
        float xv = x[n * 64 + o];
        g_xh[n * 64 + o] = __float2half_rn(xv);        // fp16 x for hidden
        float s = xv + bc2[o];
        #pragma unroll
        for (int d = 0; d < 16; d++) s += t2[d] * Wc2[d * 64 + o];
        #pragma unroll
        for (int k = 0; k < 16; k++) s += wk[k] * b2[k * 64 + o];
        out_z[n * 64 + o] = s;
    }
}

// ---------------- fused hidden + z kernel (no atomics, no smem overlay) -----
// One CTA owns 128 rows and loops over all 4 ke-blocks of 128:
//  pass1: hpre = Xh(128x64) @ W1r(128ke x 64)^T   (fp16 mma, fp32 accum)
//  epi:   h = tanh(hpre + b1); m = w(1-h^2) -> sM (flushed to g_Mh);
//         p = w*h -> sP
//  pass2: accz += P(128x128ke) @ W2t(64o x 128ke)^T   (register accum)
// After the loop: out_z[row] += accz (plain RMW, unique owner per element).
// SMEM: SX 16K | SW1 16K | SW2 16K | sM 32K | sP 32K | swt 8K | sb1 2K
#define H_SX   0
#define H_SW1  16384
#define H_SW2  32768
#define H_SM   49152
#define H_SP   81920
#define H_SWT  114688
#define H_SB1  122880
#define H_SMEM 124928

__global__ void __launch_bounds__(256)
k_hidden_f(const float* __restrict__ b1, float* __restrict__ out_z) {
    extern __shared__ char smem[];
    const uint32_t sb = smem_u32(smem);
    float* swt = (float*)(smem + H_SWT);
    float* sb1 = (float*)(smem + H_SB1);
    const int tid  = threadIdx.x;
    const int lane = tid & 31;
    const int wid  = tid >> 5;
    const int wm   = wid >> 2;        // 0..1
    const int wn   = wid & 3;         // 0..3
    const int m0 = blockIdx.x * 128;  // rows

    // --- persistent loads: X tile (cp.async), w tile, b1 (plain) ---
    {
        const char* pX = (const char*)g_xh;
        #pragma unroll
        for (int i = 0; i < 4; i++) {              // X: 128 rows x 8 x 16B
            int lin = tid + i * 256;
            int r = lin >> 3, c = lin & 7;
            CPA16(sb + H_SX + sw128(r * 128 + c * 16),
                  pX + (size_t)(m0 + r) * 128 + c * 16);
        }
        asm volatile("cp.async.commit_group;" ::: "memory");
    }
    #pragma unroll
    for (int i = 0; i < 8; i++) {
        int lin = tid + i * 256;                   // 2048 floats
        swt[lin] = g_w[(size_t)m0 * 16 + lin];
    }
    #pragma unroll
    for (int i = 0; i < 2; i++) sb1[tid + i * 256] = b1[tid + i * 256];

    // per-thread ldmatrix address components (pass 1)
    const int a_row = wm * 64 + (lane & 15);
    const int a_t   = (a_row & 7) << 4;
    const int a_kl  = (lane >> 4) * 16;
    const uint32_t a_base = (uint32_t)a_row * 128;
    const int b_row = wn * 32 + ((lane & 16) >> 1) + (lane & 7);
    const int b_t   = (b_row & 7) << 4;
    const int b_kl  = (lane & 8) * 2;
    const uint32_t b_base = (uint32_t)b_row * 128;
    const int a2_row = wid * 16 + (lane & 15);     // pass 2 A rows

    float accz[8][4];
    #pragma unroll
    for (int nt = 0; nt < 8; nt++)
        #pragma unroll
        for (int q = 0; q < 4; q++) accz[nt][q] = 0.0f;

    for (int ci = 0; ci < 4; ci++) {
        const int c0 = ci * 128;

        // --- load this ke-block's W1 (128x128B) and W2 (2 chunks 64x128B) ---
        {
            const char* pW1 = (const char*)g_w1r;
            const char* pW2 = (const char*)g_W2t;
            #pragma unroll
            for (int i = 0; i < 4; i++) {
                int lin = tid + i * 256;
                int r = lin >> 3, c = lin & 7;
                CPA16(sb + H_SW1 + sw128(r * 128 + c * 16),
                      pW1 + (size_t)(c0 + r) * 128 + c * 16);
            }
            #pragma unroll
            for (int i = 0; i < 4; i++) {
                int lin = tid + i * 256;
                int ch = lin >> 9, rem = lin & 511;
                int r = rem >> 3, c = rem & 7;
                CPA16(sb + H_SW2 + ch * 8192 + sw128(r * 128 + c * 16),
                      pW2 + (size_t)r * 1024 + (c0 + ch * 64 + c * 8) * 2);
            }
            asm volatile("cp.async.commit_group;" ::: "memory");
            asm volatile("cp.async.wait_group 0;" ::: "memory");
        }
        __syncthreads();

        // --- pass 1: hpre mma (warp tile 64 rows x 32 ke) ---
        float acc[4][4][4];
        #pragma unroll
        for (int mt = 0; mt < 4; mt++)
            #pragma unroll
            for (int nt = 0; nt < 4; nt++)
                #pragma unroll
                for (int q = 0; q < 4; q++) acc[mt][nt][q] = 0.0f;

        #pragma unroll
        for (int kk = 0; kk < 4; kk++) {
            const uint32_t akc = (uint32_t)((kk * 32 + a_kl) ^ a_t);
            const uint32_t bkc = (uint32_t)((kk * 32 + b_kl) ^ b_t);
            uint32_t Ah[4][4], Bx[2][4];
            #pragma unroll
            for (int mt = 0; mt < 4; mt++)
                ldsm4(Ah[mt], sb + H_SX + a_base + mt * 2048 + akc);
            #pragma unroll
            for (int n2 = 0; n2 < 2; n2++)
                ldsm4(Bx[n2], sb + H_SW1 + b_base + n2 * 2048 + bkc);
            #pragma unroll
            for (int mt = 0; mt < 4; mt++)
                #pragma unroll
                for (int n2 = 0; n2 < 2; n2++) {
                    mma16816(acc[mt][n2 * 2],     Ah[mt], Bx[n2][0], Bx[n2][1]);
                    mma16816(acc[mt][n2 * 2 + 1], Ah[mt], Bx[n2][2], Bx[n2][3]);
                }
        }

        // --- epilogue 1: tanh, m -> sM, p -> sP ---
        #pragma unroll
        for (int mt = 0; mt < 4; mt++) {
            #pragma unroll
            for (int qq = 0; qq < 2; qq++) {       // qq=0: rows r, qq=1: r+8
                int r_l = wm * 64 + mt * 16 + (lane >> 2) + qq * 8;
                #pragma unroll
                for (int nt = 0; nt < 4; nt++) {
                    int ke_l = wn * 32 + nt * 8 + 2 * (lane & 3);
                    float w = swt[r_l * 16 + ((c0 + ke_l) >> 5)];
                    float h0 = tanhf(acc[mt][nt][qq * 2]     + sb1[c0 + ke_l]);
                    float h1 = tanhf(acc[mt][nt][qq * 2 + 1] + sb1[c0 + ke_l + 1]);
                    __half2 mv = __floats2half2_rn(w * (1.0f - h0 * h0),
                                                   w * (1.0f - h1 * h1));
                    __half2 pv = __floats2half2_rn(w * h0, w * h1);
                    int ch = ke_l >> 6;
                    uint32_t off = sw128((uint32_t)r_l * 128 + (ke_l & 63) * 2);
                    *(__half2*)(smem + H_SM + ch * 16384 + off) = mv;
                    *(__half2*)(smem + H_SP + ch * 16384 + off) = pv;
                }
            }
        }
        __syncthreads();

        // --- flush M tile to g_Mh (coalesced uint4) ---
        #pragma unroll
        for (int i = 0; i < 8; i++) {
            int lin = tid + i * 256;               // 2048 uint4
            int r = lin >> 4, c16 = lin & 15;
            int ch = c16 >> 3;
            uint32_t soff = sw128((uint32_t)r * 128 + (c16 & 7) * 16);
            uint4 v = *(uint4*)(smem + H_SM + ch * 16384 + soff);
            *(uint4*)((char*)g_Mh + (size_t)(m0 + r) * 1024
                      + (c0 + c16 * 8) * 2) = v;
        }

        // --- pass 2: accz += P @ W2t (warp = 16 rows x 64 cols) ---
        #pragma unroll
        for (int ck = 0; ck < 8; ck++) {
            int ch = ck >> 2, kk = ck & 3;
            uint32_t aoff = sw128((uint32_t)a2_row * 128 + kk * 32 + a_kl);
            uint32_t Ah2[4];
            ldsm4(Ah2, sb + H_SP + ch * 16384 + aoff);
            #pragma unroll
            for (int n2 = 0; n2 < 4; n2++) {       // 4 x 16 o-rows
                int brow = n2 * 16 + ((lane & 16) >> 1) + (lane & 7);
                uint32_t boff = sw128((uint32_t)brow * 128 + kk * 32 + b_kl);
                uint32_t Bx2[4];
                ldsm4(Bx2, sb + H_SW2 + ch * 8192 + boff);
                mma16816(accz[n2 * 2],     Ah2, Bx2[0], Bx2[1]);
                mma16816(accz[n2 * 2 + 1], Ah2, Bx2[2], Bx2[3]);
            }
        }
        __syncthreads();   // all reads done before next iter overwrites smem
    }

    // --- final: out_z += accz (unique owner per element, plain RMW) ---
    #pragma unroll
    for (int nt = 0; nt < 8; nt++) {
        int o = nt * 8 + 2 * (lane & 3);
        size_t r = (size_t)m0 + wid * 16 + (lane >> 2);
        float2* p0 = (float2*)&out_z[r * 64 + o];
        float2* p1 = (float2*)&out_z[(r + 8) * 64 + o];
        float2 v0 = *p0, v1 = *p1;
        v0.x += accz[nt][0]; v0.y += accz[nt][1];
        v1.x += accz[nt][2]; v1.y += accz[nt][3];
        *p0 = v0; *p1 = v1;
    }
}

// ---------------- jac GEMM via mma.sync fp16, occupancy-2 -------------------
// out_j(32768x4096) = I + fp16(M)(32768x512) @ fp16(B)(512x4096)
// CTA tile 128(M) x 128(N), 8 warps (2m x 4n), warp tile 64x32.
// K chunks of 64, double-buffered cp.async, SW128-swizzled smem for ldmatrix.
// Stage: Ah 16K | Bh 16K = 32KB; 2 stages = 64KB; 2 CTAs/SM so one CTA's
// DRAM-bound fp32 epilogue overlaps the other's tensor-bound mainloop.
#define J_TM 128
#define J_TN 128
#define J_KB 64
#define J_NKT 8
#define J_ST_SZ 32768
#define J_SMEM (2 * J_ST_SZ)

__device__ __forceinline__ void j_issue(uint32_t stage, int m0, int c0,
                                        int kt, int tid) {
    const char* pMh = (const char*)g_Mh;
    const char* pBh = (const char*)g_Bh;
    #pragma unroll
    for (int i = 0; i < 4; i++) {                  // A: 128 rows x 8 x 16B
        int lin = tid + i * 256;
        int r = lin >> 3, c = lin & 7;
        uint32_t sw = sw128(r * 128 + c * 16);
        size_t go = ((size_t)(m0 + r) * 512 + kt * J_KB + c * 8) * 2;
        CPA16(stage + sw, pMh + go);
    }
    #pragma unroll
    for (int i = 0; i < 4; i++) {                  // B: 128 rows x 8 x 16B
        int lin = tid + i * 256;
        int r = lin >> 3, c = lin & 7;
        uint32_t sw = sw128(r * 128 + c * 16);
        size_t go = ((size_t)(c0 + r) * 512 + kt * J_KB + c * 8) * 2;
        CPA16(stage + 16384 + sw, pBh + go);
    }
    asm volatile("cp.async.commit_group;" ::: "memory");
}

__global__ void __launch_bounds__(256, 2)
k_jac_mma(float* __restrict__ out_j) {
    extern __shared__ char smem[];
    const uint32_t sb = smem_u32(smem);
    const int tid  = threadIdx.x;
    const int lane = tid & 31;
    const int wid  = tid >> 5;
    const int wm   = wid >> 2;      // 0..1
    const int wn   = wid & 3;       // 0..3
    const int c0 = blockIdx.x * J_TN;
    const int m0 = blockIdx.y * J_TM;

    // ldmatrix per-thread address components (same form as k_hidden_f pass 1)
    const int a_row = wm * 64 + (lane & 15);
    const int a_t   = (a_row & 7) << 4;
    const int a_kl  = (lane >> 4) * 16;            // bytes
    const uint32_t a_base = (uint32_t)a_row * 128;
    const int b_row = wn * 32 + ((lane & 16) >> 1) + (lane & 7);
    const int b_t   = (b_row & 7) << 4;
    const int b_kl  = (lane & 8) * 2;              // bytes
    const uint32_t b_base = (uint32_t)b_row * 128;

    float acc[4][4][4];
    #pragma unroll
    for (int mt = 0; mt < 4; mt++)
        #pragma unroll
        for (int nt = 0; nt < 4; nt++)
            #pragma unroll
            for (int q = 0; q < 4; q++) acc[mt][nt][q] = 0.0f;

    j_issue(sb,           m0, c0, 0, tid);
    j_issue(sb + J_ST_SZ, m0, c0, 1, tid);

    for (int kt = 0; kt < J_NKT; kt++) {
        if (kt < J_NKT - 1)
            asm volatile("cp.async.wait_group 1;" ::: "memory");
        else
            asm volatile("cp.async.wait_group 0;" ::: "memory");
        __syncthreads();

        const uint32_t st = sb + (kt & 1) * J_ST_SZ;
        const uint32_t sAh = st;
        const uint32_t sBh = st + 16384;

        #pragma unroll
        for (int kk = 0; kk < 4; kk++) {
            const uint32_t akc = (uint32_t)((kk * 32 + a_kl) ^ a_t);
            const uint32_t bkc = (uint32_t)((kk * 32 + b_kl) ^ b_t);
            uint32_t Ah[4][4], Bx[2][4];
            #pragma unroll
            for (int mt = 0; mt < 4; mt++)
                ldsm4(Ah[mt], sAh + a_base + mt * 2048 + akc);
            #pragma unroll
            for (int n2 = 0; n2 < 2; n2++)
                ldsm4(Bx[n2], sBh + b_base + n2 * 2048 + bkc);
            #pragma unroll
            for (int mt = 0; mt < 4; mt++)
                #pragma unroll
                for (int n2 = 0; n2 < 2; n2++) {
                    mma16816(acc[mt][n2 * 2],     Ah[mt], Bx[n2][0], Bx[n2][1]);
                    mma16816(acc[mt][n2 * 2 + 1], Ah[mt], Bx[n2][2], Bx[n2][3]);
                }
        }
        __syncthreads();
        if (kt + 2 < J_NKT)
            j_issue(sb + (kt & 1) * J_ST_SZ, m0, c0, kt + 2, tid);
    }

    // epilogue: identity on columns with c % 65 == 0 (independent of row)
    #pragma unroll
    for (int mt = 0; mt < 4; mt++) {
        size_t r0 = (size_t)m0 + wm * 64 + mt * 16 + (lane >> 2);
        #pragma unroll
        for (int nt = 0; nt < 4; nt++) {
            int c = c0 + wn * 32 + nt * 8 + 2 * (lane & 3);
            float add0 = ((c % 65) == 0) ? 1.0f : 0.0f;
            float add1 = (((c + 1) % 65) == 0) ? 1.0f : 0.0f;
            float2 v0 = make_float2(acc[mt][nt][0] + add0, acc[mt][nt][1] + add1);
            float2 v1 = make_float2(acc[mt][nt][2] + add0, acc[mt][nt][3] + add1);
            *(float2*)&out_j[r0 * 4096 + c]       = v0;
            *(float2*)&out_j[(r0 + 8) * 4096 + c] = v1;
        }
    }
}

// ---------------- launch ----------------------------------------------------
extern "C" void kernel_launch(void* const* d_in, const int* in_sizes, int n_in,
                              void* d_out, int out_size) {
    const float* x    = (const float*)d_in[0];
    const float* y    = (const float*)d_in[1];
    const float* W1   = (const float*)d_in[2];
    const float* b1   = (const float*)d_in[3];
    const float* W2   = (const float*)d_in[4];
    const float* b2   = (const float*)d_in[5];
    const float* Wb1  = (const float*)d_in[6];
    const float* bb1  = (const float*)d_in[7];
    const float* Wb2  = (const float*)d_in[8];
    const float* bb2  = (const float*)d_in[9];
    const float* Wc1  = (const float*)d_in[10];
    const float* bc1  = (const float*)d_in[11];
    const float* Wc2  = (const float*)d_in[12];
    const float* bc2  = (const float*)d_in[13];
    const float* mean = (const float*)d_in[14];
    const float* var  = (const float*)d_in[15];

    float* out   = (float*)d_out;
    float* out_z = out;                       // N*64
    float* out_j = out + (size_t)NN * NX;     // N*4096

    cudaFuncSetAttribute(k_jac_mma, cudaFuncAttributeMaxDynamicSharedMemorySize,
                         J_SMEM);
    cudaFuncSetAttribute(k_hidden_f, cudaFuncAttributeMaxDynamicSharedMemorySize,
                         H_SMEM);

    k_prep_small<<<128, 256>>>(W1, W2);
    k_prep_Bt<<<8192, 256>>>(W1, W2);
    k_branch<<<NN / 8, 256>>>(x, y, b2, Wb1, bb1, Wb2, bb2,
                              Wc1, bc1, Wc2, bc2, mean, var, out_z);
    k_hidden_f<<<NN / 128, 256, H_SMEM>>>(b1, out_z);
    k_jac_mma<<<dim3(OUTC / J_TN, NN / J_TM), 256, J_SMEM>>>(out_j);
}